// round 4
// baseline (speedup 1.0000x reference)
#include <cuda_runtime.h>
#include <cuda_bf16.h>
#include <math.h>

// Problem constants
#define BB   32
#define TT   127
#define SS   256
#define HH   512
#define VV   8000
#define NHH  8
#define HDD  64
#define BT   (BB*TT)      // 4064
#define BS   (BB*SS)      // 8192
#define NBLK 128          // persistent LSTM grid (must all be co-resident)

// ---------------- scratch (device globals; no allocations allowed) ----------------
__device__ float g_emb [BT * HH];        // embedded targets
__device__ float g_xg  [BT * 4 * HH];    // precomputed input gates
__device__ float g_h   [2][BB * HH];     // ping-pong hidden state
__device__ float g_lstm[BT * HH];        // lstm outputs
__device__ float g_q   [BT * HH];
__device__ float g_k   [BS * HH];
__device__ float g_v   [BS * HH];
__device__ float g_ctx [BT * HH];
__device__ float g_comb[BT * HH];
__device__ unsigned g_bar;               // arrival counter (RMW line)
__device__ unsigned g_epoch;             // release flag (separate line for pollers)

// ---------------- cp.async helpers ----------------
__device__ __forceinline__ void cp_async16(float* dst_smem, const float* src_gmem) {
    unsigned s = (unsigned)__cvta_generic_to_shared(dst_smem);
    asm volatile("cp.async.cg.shared.global [%0], [%1], 16;\n" :: "r"(s), "l"(src_gmem));
}
__device__ __forceinline__ void cp_async_commit() { asm volatile("cp.async.commit_group;\n"); }
#define CP_WAIT(n) asm volatile("cp.async.wait_group %0;\n" :: "n"(n))

// ---------------- init: zero h0 and barrier state ----------------
__global__ void zero_kernel(float* h0, int n) {
    int i = blockIdx.x * blockDim.x + threadIdx.x;
    if (i < n) h0[i] = 0.f;
    if (i == 0) { g_bar = 0u; g_epoch = 0u; }
}

// ---------------- embedding gather ----------------
__global__ void gather_kernel(const int* __restrict__ targets,
                              const float* __restrict__ table,
                              float* __restrict__ out) {
    int bt = blockIdx.x;                 // 0..4063
    int b = bt / TT, t = bt - b * TT;
    int tok = targets[b * 128 + t];      // targets is [B,128], use [:, :-1]
    const float4* src = (const float4*)(table + (size_t)tok * HH);
    float4* dst = (float4*)(out + (size_t)bt * HH);
    dst[threadIdx.x] = src[threadIdx.x]; // 128 threads * float4 = 512 floats
}

// ---------------- generic SGEMM: C[M,N] = A[M,K] @ B[N,K]^T + bias1 + bias2 + res ----------------
__global__ __launch_bounds__(256) void sgemm_kernel(
    const float* __restrict__ A, const float* __restrict__ B,
    const float* __restrict__ bias1, const float* __restrict__ bias2,
    const float* __restrict__ res, float* __restrict__ C,
    int M, int N, int K)
{
    __shared__ float As[8][128];
    __shared__ float Bs[8][128];
    const int bm = blockIdx.y * 128;
    const int bn = blockIdx.x * 128;
    const int tid = threadIdx.x;
    const int lr = tid >> 1;            // 0..127 (load row)
    const int lc = (tid & 1) << 2;      // 0 or 4 (load col group)
    const int tx = tid & 15;            // n-tile
    const int ty = tid >> 4;            // m-tile

    float acc[8][8];
    #pragma unroll
    for (int i = 0; i < 8; i++)
        #pragma unroll
        for (int j = 0; j < 8; j++) acc[i][j] = 0.f;

    const bool aval = (bm + lr) < M;
    const bool bval = (bn + lr) < N;
    const float* Aptr = A + (size_t)(bm + lr) * K + lc;
    const float* Bptr = B + (size_t)(bn + lr) * K + lc;
    const float4 zero4 = make_float4(0.f, 0.f, 0.f, 0.f);

    for (int k0 = 0; k0 < K; k0 += 8) {
        float4 a4 = aval ? *(const float4*)(Aptr + k0) : zero4;
        float4 b4 = bval ? *(const float4*)(Bptr + k0) : zero4;
        As[lc + 0][lr] = a4.x; As[lc + 1][lr] = a4.y;
        As[lc + 2][lr] = a4.z; As[lc + 3][lr] = a4.w;
        Bs[lc + 0][lr] = b4.x; Bs[lc + 1][lr] = b4.y;
        Bs[lc + 2][lr] = b4.z; Bs[lc + 3][lr] = b4.w;
        __syncthreads();
        #pragma unroll
        for (int kk = 0; kk < 8; kk++) {
            float ra[8], rb[8];
            *(float4*)(ra)     = *(const float4*)(&As[kk][ty * 8]);
            *(float4*)(ra + 4) = *(const float4*)(&As[kk][ty * 8 + 4]);
            *(float4*)(rb)     = *(const float4*)(&Bs[kk][tx * 8]);
            *(float4*)(rb + 4) = *(const float4*)(&Bs[kk][tx * 8 + 4]);
            #pragma unroll
            for (int i = 0; i < 8; i++)
                #pragma unroll
                for (int j = 0; j < 8; j++)
                    acc[i][j] += ra[i] * rb[j];
        }
        __syncthreads();
    }

    #pragma unroll
    for (int i = 0; i < 8; i++) {
        int row = bm + ty * 8 + i;
        if (row >= M) continue;
        #pragma unroll
        for (int j = 0; j < 8; j++) {
            int col = bn + tx * 8 + j;
            if (col >= N) continue;
            float v = acc[i][j];
            if (bias1) v += bias1[col];
            if (bias2) v += bias2[col];
            if (res)   v += res[(size_t)row * N + col];
            C[(size_t)row * N + col] = v;
        }
    }
}

// ---------------- persistent LSTM: all 127 steps, 128 blocks x 512 threads ----------------
// Block j owns h-columns [4j,4j+4) -> 16 gate rows. Thread (b=tid>>4, cc=tid&15)
// computes one gate pre-activation for batch b, local gate-row cc.
// w slice in smem for whole kernel; c-state in registers (threads with cc<4).
// h staged per step in 4 pipelined cp.async chunks. Grid barrier: counter + epoch flag.
#define HP 516   // h smem pitch (floats)
#define WP 516   // w smem pitch (floats)
__global__ __launch_bounds__(512) void lstm_persistent_kernel(
    const float* __restrict__ xg, const float* __restrict__ w_hh,
    float* __restrict__ hbuf0, float* __restrict__ hbuf1,
    float* __restrict__ lstm_out)
{
    extern __shared__ float smem[];
    float* h_sm = smem;                    // 32 * HP
    float* w_sm = smem + 32 * HP;          // 16 * WP

    const int tid = threadIdx.x;
    const int c0  = blockIdx.x * 4;

    // Load 16 w_hh rows (4 gates x 4 cols) once for the entire kernel.
    for (int idx = tid; idx < 16 * 128; idx += 512) {
        int r = idx >> 7; int k4 = (idx & 127) << 2;
        int gr = (r >> 2) * HH + c0 + (r & 3);
        float4 v = *(const float4*)(w_hh + (size_t)gr * HH + k4);
        float* d = w_sm + r * WP + k4;
        d[0] = v.x; d[1] = v.y; d[2] = v.z; d[3] = v.w;
    }

    const int b  = tid >> 4;          // batch 0..31
    const int cc = tid & 15;          // local gate row: q=cc>>2 (i,f,g,o), lc=cc&3
    const int col = (cc >> 2) * HH + c0 + (cc & 3);   // column into xg's 2048
    const float* wrow = w_sm + cc * WP;
    const float* hrow = h_sm + b * HP;
    const size_t xgbase = (size_t)(b * TT) * (4 * HH) + col;
    const bool is_act = (cc < 4);     // lanes that do activation (own column c0+cc)
    const int hcol = c0 + (cc & 3);
    float c_reg = 0.f;

    __syncthreads();   // w_sm ready

    for (int t = 0; t < TT; t++) {
        const float* hprev = (t & 1) ? hbuf1 : hbuf0;
        float*       hnext = (t & 1) ? hbuf0 : hbuf1;

        // issue 4 cp.async chunk groups: chunk c = floats [128c,128c+128) of every batch row
        #pragma unroll
        for (int c = 0; c < 4; c++) {
            #pragma unroll
            for (int i = 0; i < 2; i++) {
                int idx = tid + i * 512;          // 0..1023
                int bb = idx >> 5; int k4 = (((idx & 31) + c * 32)) << 2;
                cp_async16(h_sm + bb * HP + k4, hprev + bb * HH + k4);
            }
            cp_async_commit();
        }

        // prefetch xg while copies are in flight
        float xgv = __ldg(xg + xgbase + (size_t)t * (4 * HH));

        // chunk-pipelined dot product: a = w[cc] . h[b]
        float a0 = 0.f, a1 = 0.f;
        #define DOT_CHUNK(C)                                                  \
        {                                                                     \
            const float* wr = wrow + (C) * 128;                               \
            const float* hr = hrow + (C) * 128;                               \
            _Pragma("unroll")                                                 \
            for (int k = 0; k < 128; k += 8) {                                \
                float4 w0 = *(const float4*)(wr + k);                         \
                float4 w1 = *(const float4*)(wr + k + 4);                     \
                float4 h0 = *(const float4*)(hr + k);                         \
                float4 h1 = *(const float4*)(hr + k + 4);                     \
                a0 = fmaf(w0.x, h0.x, a0); a1 = fmaf(w1.x, h1.x, a1);         \
                a0 = fmaf(w0.y, h0.y, a0); a1 = fmaf(w1.y, h1.y, a1);         \
                a0 = fmaf(w0.z, h0.z, a0); a1 = fmaf(w1.z, h1.z, a1);         \
                a0 = fmaf(w0.w, h0.w, a0); a1 = fmaf(w1.w, h1.w, a1);         \
            }                                                                 \
        }
        CP_WAIT(3); __syncthreads(); DOT_CHUNK(0);
        CP_WAIT(2); __syncthreads(); DOT_CHUNK(1);
        CP_WAIT(1); __syncthreads(); DOT_CHUNK(2);
        CP_WAIT(0); __syncthreads(); DOT_CHUNK(3);
        #undef DOT_CHUNK

        float gate = a0 + a1 + xgv;

        // gather f,g,o gates from lanes +4,+8,+12 (same warp, same batch)
        float fv = __shfl_down_sync(0xffffffffu, gate, 4);
        float gv = __shfl_down_sync(0xffffffffu, gate, 8);
        float ov = __shfl_down_sync(0xffffffffu, gate, 12);

        if (is_act) {
            float ig = 1.f / (1.f + __expf(-gate));
            float fg = 1.f / (1.f + __expf(-fv));
            float og = 1.f / (1.f + __expf(-ov));
            float gg = tanhf(gv);
            c_reg = fg * c_reg + ig * gg;
            float hn = og * tanhf(c_reg);
            __stcg(hnext + b * HH + hcol, hn);
            __stcg(lstm_out + (size_t)(b * TT + t) * HH + hcol, hn);
        }
        __threadfence();
        __syncthreads();

        // grid barrier: arrivals on g_bar; last arriver publishes epoch (separate line)
        if (tid == 0) {
            unsigned old = atomicAdd(&g_bar, 1u);
            if (old == (unsigned)(t + 1) * NBLK - 1u) {
                asm volatile("st.release.gpu.global.u32 [%0], %1;"
                             :: "l"(&g_epoch), "r"((unsigned)(t + 1)) : "memory");
            } else {
                unsigned e;
                do {
                    asm volatile("ld.acquire.gpu.global.u32 %0, [%1];"
                                 : "=r"(e) : "l"(&g_epoch) : "memory");
                } while (e < (unsigned)(t + 1));
            }
        }
        __syncthreads();
    }
}

// ---------------- fused attention: per (t-chunk, head, batch) ----------------
#define KTP 257   // transposed K/V pitch (257 mod 32 == 1 -> conflict-free lane stride)
#define QSP 68
#define PSP 260
__global__ __launch_bounds__(256) void attn_kernel(
    const float* __restrict__ q, const float* __restrict__ kmat,
    const float* __restrict__ vmat, float* __restrict__ ctx)
{
    extern __shared__ float smem[];
    float* Kt   = smem;                    // [64][KTP]
    float* Vt   = Kt + 64 * KTP;           // [64][KTP]
    float* qs   = Vt + 64 * KTP;           // [32][QSP]
    float* ps   = qs + 32 * QSP;           // [32][PSP]
    float* sums = ps + 32 * PSP;           // [32]

    const int t0 = blockIdx.x * 32;
    const int h  = blockIdx.y;
    const int b  = blockIdx.z;
    const int tid = threadIdx.x;

    // load K,V transposed: Kt[d][s] = K[b*256+s][h*64+d]
    for (int idx = tid; idx < 256 * 16; idx += 256) {
        int s = idx >> 4; int d4 = (idx & 15) << 2;
        size_t off = (size_t)(b * SS + s) * HH + h * HDD + d4;
        float4 kv = *(const float4*)(kmat + off);
        Kt[(d4 + 0) * KTP + s] = kv.x; Kt[(d4 + 1) * KTP + s] = kv.y;
        Kt[(d4 + 2) * KTP + s] = kv.z; Kt[(d4 + 3) * KTP + s] = kv.w;
        float4 vv = *(const float4*)(vmat + off);
        Vt[(d4 + 0) * KTP + s] = vv.x; Vt[(d4 + 1) * KTP + s] = vv.y;
        Vt[(d4 + 2) * KTP + s] = vv.z; Vt[(d4 + 3) * KTP + s] = vv.w;
    }
    // load q chunk
    for (int idx = tid; idx < 32 * 16; idx += 256) {
        int r = idx >> 4; int d4 = (idx & 15) << 2;
        int trow = t0 + r;
        float4 qv = make_float4(0.f, 0.f, 0.f, 0.f);
        if (trow < TT)
            qv = *(const float4*)(q + (size_t)(b * TT + trow) * HH + h * HDD + d4);
        float* d = qs + r * QSP + d4;
        d[0] = qv.x; d[1] = qv.y; d[2] = qv.z; d[3] = qv.w;
    }
    __syncthreads();

    const int r  = tid >> 3;  // query row in chunk
    const int lc = tid & 7;   // lane-col

    float qreg[64];
    #pragma unroll
    for (int d = 0; d < 64; d++) qreg[d] = qs[r * QSP + d];

    float sc[32];
    for (int si = 0; si < 32; si++) {
        int s = si * 8 + lc;
        float acc = 0.f;
        #pragma unroll
        for (int d = 0; d < 64; d++) acc += qreg[d] * Kt[d * KTP + s];
        sc[si] = acc * 0.125f;   // 1/sqrt(64)
    }
    float m = -1e30f;
    #pragma unroll
    for (int si = 0; si < 32; si++) m = fmaxf(m, sc[si]);
    m = fmaxf(m, __shfl_xor_sync(0xffffffff, m, 1));
    m = fmaxf(m, __shfl_xor_sync(0xffffffff, m, 2));
    m = fmaxf(m, __shfl_xor_sync(0xffffffff, m, 4));
    float ssum = 0.f;
    #pragma unroll
    for (int si = 0; si < 32; si++) {
        float e = __expf(sc[si] - m);
        ssum += e;
        ps[r * PSP + si * 8 + lc] = e;
    }
    ssum += __shfl_xor_sync(0xffffffff, ssum, 1);
    ssum += __shfl_xor_sync(0xffffffff, ssum, 2);
    ssum += __shfl_xor_sync(0xffffffff, ssum, 4);
    if (lc == 0) sums[r] = ssum;
    __syncthreads();

    // ctx: thread covers d = lc + 8j
    float accv[8];
    #pragma unroll
    for (int j = 0; j < 8; j++) accv[j] = 0.f;
    const float* prow = ps + r * PSP;
    #pragma unroll 4
    for (int s = 0; s < 256; s++) {
        float pv = prow[s];
        #pragma unroll
        for (int j = 0; j < 8; j++)
            accv[j] += pv * Vt[(lc + 8 * j) * KTP + s];
    }
    float inv = 1.0f / sums[r];
    int trow = t0 + r;
    if (trow < TT) {
        float* dst = ctx + (size_t)(b * TT + trow) * HH + h * HDD;
        #pragma unroll
        for (int j = 0; j < 8; j++) dst[lc + 8 * j] = accv[j] * inv;
    }
}

// ---------------- launch ----------------
extern "C" void kernel_launch(void* const* d_in, const int* in_sizes, int n_in,
                              void* d_out, int out_size) {
    const int*   targets  = (const int*)  d_in[0];
    const float* enc      = (const float*)d_in[1];
    const float* embedding= (const float*)d_in[2];
    const float* w_ih     = (const float*)d_in[3];
    const float* w_hh     = (const float*)d_in[4];
    const float* b_ih     = (const float*)d_in[5];
    const float* b_hh     = (const float*)d_in[6];
    const float* in_proj_w= (const float*)d_in[7];
    const float* in_proj_b= (const float*)d_in[8];
    const float* out_proj_w=(const float*)d_in[9];
    const float* out_proj_b=(const float*)d_in[10];
    const float* fc_w     = (const float*)d_in[11];
    const float* fc_b     = (const float*)d_in[12];
    float* out = (float*)d_out;

    float *p_emb, *p_xg, *p_h, *p_lstm, *p_q, *p_k, *p_v, *p_ctx, *p_comb;
    cudaGetSymbolAddress((void**)&p_emb,  g_emb);
    cudaGetSymbolAddress((void**)&p_xg,   g_xg);
    cudaGetSymbolAddress((void**)&p_h,    g_h);
    cudaGetSymbolAddress((void**)&p_lstm, g_lstm);
    cudaGetSymbolAddress((void**)&p_q,    g_q);
    cudaGetSymbolAddress((void**)&p_k,    g_k);
    cudaGetSymbolAddress((void**)&p_v,    g_v);
    cudaGetSymbolAddress((void**)&p_ctx,  g_ctx);
    cudaGetSymbolAddress((void**)&p_comb, g_comb);
    float* h_buf0 = p_h;
    float* h_buf1 = p_h + BB * HH;

    // request extra smem so only one block fits per SM (guarantees 128-block co-residency layout)
    const int lstm_smem = 118 * 1024;
    const int attn_smem = (64 * KTP * 2 + 32 * QSP + 32 * PSP + 32) * (int)sizeof(float);
    cudaFuncSetAttribute(lstm_persistent_kernel, cudaFuncAttributeMaxDynamicSharedMemorySize, lstm_smem);
    cudaFuncSetAttribute(attn_kernel,            cudaFuncAttributeMaxDynamicSharedMemorySize, attn_smem);

    // 1. zero h0 + barrier state
    zero_kernel<<<(BB * HH + 255) / 256, 256>>>(h_buf0, BB * HH);

    // 2. gather embeddings
    gather_kernel<<<BT, 128>>>(targets, embedding, p_emb);

    // 3. xg = emb @ w_ih^T + b_ih + b_hh   [4064, 2048]
    {
        dim3 grid((4 * HH + 127) / 128, (BT + 127) / 128);
        sgemm_kernel<<<grid, 256>>>(p_emb, w_ih, b_ih, b_hh, nullptr, p_xg, BT, 4 * HH, HH);
    }

    // 4. LSTM recurrence — one persistent kernel for all 127 steps
    lstm_persistent_kernel<<<NBLK, 512, lstm_smem>>>(p_xg, w_hh, h_buf0, h_buf1, p_lstm);

    // 5. q/k/v projections
    {
        dim3 gq((HH + 127) / 128, (BT + 127) / 128);
        sgemm_kernel<<<gq, 256>>>(p_lstm, in_proj_w, in_proj_b, nullptr, nullptr, p_q, BT, HH, HH);
        dim3 gk((HH + 127) / 128, (BS + 127) / 128);
        sgemm_kernel<<<gk, 256>>>(enc, in_proj_w + (size_t)HH * HH, in_proj_b + HH,
                                  nullptr, nullptr, p_k, BS, HH, HH);
        sgemm_kernel<<<gk, 256>>>(enc, in_proj_w + (size_t)2 * HH * HH, in_proj_b + 2 * HH,
                                  nullptr, nullptr, p_v, BS, HH, HH);
    }

    // 6. fused attention -> ctx
    {
        dim3 grid(4, NHH, BB);
        attn_kernel<<<grid, 256, attn_smem>>>(p_q, p_k, p_v, p_ctx);
    }

    // 7. combined = ctx @ out_proj^T + out_proj_b + lstm_out
    {
        dim3 grid((HH + 127) / 128, (BT + 127) / 128);
        sgemm_kernel<<<grid, 256>>>(p_ctx, out_proj_w, out_proj_b, nullptr, p_lstm, p_comb, BT, HH, HH);
    }

    // 8. out = combined @ fc_w^T + fc_b   [4064, 8000]
    {
        dim3 grid((VV + 127) / 128, (BT + 127) / 128);
        sgemm_kernel<<<grid, 256>>>(p_comb, fc_w, fc_b, nullptr, nullptr, out, BT, VV, HH);
    }
}

// round 5
// speedup vs baseline: 1.0282x; 1.0282x over previous
#include <cuda_runtime.h>
#include <cuda_bf16.h>
#include <math.h>

// Problem constants
#define BB   32
#define TT   127
#define SS   256
#define HH   512
#define VV   8000
#define NHH  8
#define HDD  64
#define BT   (BB*TT)      // 4064
#define BS   (BB*SS)      // 8192
#define NBLK 128          // persistent LSTM grid (4 groups x 32 blocks)
#define GRPB 8            // batches per group

// ---------------- scratch (device globals; no allocations allowed) ----------------
__device__ float g_emb [BT * HH];        // embedded targets
__device__ float g_xg  [BT * 4 * HH];    // precomputed input gates
__device__ float g_h   [2][BB * HH];     // ping-pong hidden state
__device__ float g_lstm[BT * HH];        // lstm outputs
__device__ float g_q   [BT * HH];
__device__ float g_k   [BS * HH];
__device__ float g_v   [BS * HH];
__device__ float g_ctx [BT * HH];
__device__ float g_comb[BT * HH];
__device__ unsigned g_flags[NBLK * 32];  // per-block step flags, 128B padded

// ---------------- cp.async helpers ----------------
__device__ __forceinline__ void cp_async16(float* dst_smem, const float* src_gmem) {
    unsigned s = (unsigned)__cvta_generic_to_shared(dst_smem);
    asm volatile("cp.async.cg.shared.global [%0], [%1], 16;\n" :: "r"(s), "l"(src_gmem));
}
__device__ __forceinline__ void cp_async_commit() { asm volatile("cp.async.commit_group;\n"); }
#define CP_WAIT(n) asm volatile("cp.async.wait_group %0;\n" :: "n"(n))

// ---------------- init: zero h0 and flags ----------------
__global__ void zero_kernel(float* h0, int n) {
    int i = blockIdx.x * blockDim.x + threadIdx.x;
    if (i < n) h0[i] = 0.f;
    if (i < NBLK * 32) g_flags[i] = 0u;
}

// ---------------- embedding gather ----------------
__global__ void gather_kernel(const int* __restrict__ targets,
                              const float* __restrict__ table,
                              float* __restrict__ out) {
    int bt = blockIdx.x;                 // 0..4063
    int b = bt / TT, t = bt - b * TT;
    int tok = targets[b * 128 + t];      // targets is [B,128], use [:, :-1]
    const float4* src = (const float4*)(table + (size_t)tok * HH);
    float4* dst = (float4*)(out + (size_t)bt * HH);
    dst[threadIdx.x] = src[threadIdx.x]; // 128 threads * float4 = 512 floats
}

// ---------------- generic SGEMM: C[M,N] = A[M,K] @ B[N,K]^T + bias1 + bias2 + res ----------------
__global__ __launch_bounds__(256) void sgemm_kernel(
    const float* __restrict__ A, const float* __restrict__ B,
    const float* __restrict__ bias1, const float* __restrict__ bias2,
    const float* __restrict__ res, float* __restrict__ C,
    int M, int N, int K)
{
    __shared__ float As[8][128];
    __shared__ float Bs[8][128];
    const int bm = blockIdx.y * 128;
    const int bn = blockIdx.x * 128;
    const int tid = threadIdx.x;
    const int lr = tid >> 1;            // 0..127 (load row)
    const int lc = (tid & 1) << 2;      // 0 or 4 (load col group)
    const int tx = tid & 15;            // n-tile
    const int ty = tid >> 4;            // m-tile

    float acc[8][8];
    #pragma unroll
    for (int i = 0; i < 8; i++)
        #pragma unroll
        for (int j = 0; j < 8; j++) acc[i][j] = 0.f;

    const bool aval = (bm + lr) < M;
    const bool bval = (bn + lr) < N;
    const float* Aptr = A + (size_t)(bm + lr) * K + lc;
    const float* Bptr = B + (size_t)(bn + lr) * K + lc;
    const float4 zero4 = make_float4(0.f, 0.f, 0.f, 0.f);

    for (int k0 = 0; k0 < K; k0 += 8) {
        float4 a4 = aval ? *(const float4*)(Aptr + k0) : zero4;
        float4 b4 = bval ? *(const float4*)(Bptr + k0) : zero4;
        As[lc + 0][lr] = a4.x; As[lc + 1][lr] = a4.y;
        As[lc + 2][lr] = a4.z; As[lc + 3][lr] = a4.w;
        Bs[lc + 0][lr] = b4.x; Bs[lc + 1][lr] = b4.y;
        Bs[lc + 2][lr] = b4.z; Bs[lc + 3][lr] = b4.w;
        __syncthreads();
        #pragma unroll
        for (int kk = 0; kk < 8; kk++) {
            float ra[8], rb[8];
            *(float4*)(ra)     = *(const float4*)(&As[kk][ty * 8]);
            *(float4*)(ra + 4) = *(const float4*)(&As[kk][ty * 8 + 4]);
            *(float4*)(rb)     = *(const float4*)(&Bs[kk][tx * 8]);
            *(float4*)(rb + 4) = *(const float4*)(&Bs[kk][tx * 8 + 4]);
            #pragma unroll
            for (int i = 0; i < 8; i++)
                #pragma unroll
                for (int j = 0; j < 8; j++)
                    acc[i][j] += ra[i] * rb[j];
        }
        __syncthreads();
    }

    #pragma unroll
    for (int i = 0; i < 8; i++) {
        int row = bm + ty * 8 + i;
        if (row >= M) continue;
        #pragma unroll
        for (int j = 0; j < 8; j++) {
            int col = bn + tx * 8 + j;
            if (col >= N) continue;
            float v = acc[i][j];
            if (bias1) v += bias1[col];
            if (bias2) v += bias2[col];
            if (res)   v += res[(size_t)row * N + col];
            C[(size_t)row * N + col] = v;
        }
    }
}

// ---------------- persistent LSTM: 4 groups x 32 blocks, 512 threads ----------------
// Group g owns batches [8g, 8g+8). Its 32 blocks split the 512 h-columns:
// block slot s owns columns [16s, 16s+16) -> 64 gate rows (128KB weights in smem, loaded once).
// warp w handles column col_base+w; lane = q*8+b (gate q, batch b).
// Per step: poll group flags -> stage 16KB h -> dot -> shfl gate gather -> act -> store h -> publish flag.
#define LHP 516   // h smem pitch (8b mod 32 -> distinct banks)
#define LWP 516   // w smem pitch
__global__ __launch_bounds__(512) void lstm_persistent_kernel(
    const float* __restrict__ xg, const float* __restrict__ w_hh,
    float* __restrict__ hbuf0, float* __restrict__ hbuf1,
    float* __restrict__ lstm_out)
{
    extern __shared__ float smem[];
    float* h_sm = smem;                    // 8 * LHP
    float* w_sm = smem + 8 * LHP;          // 64 * LWP

    const int tid   = threadIdx.x;
    const int group = blockIdx.x >> 5;     // 0..3
    const int gslot = blockIdx.x & 31;     // 0..31
    const int b_base   = group * GRPB;
    const int col_base = gslot * 16;

    // Load 64 w_hh rows (16 cols x 4 gates) once. row r = w*4+q -> gate row q*512 + col_base + w.
    for (int idx = tid; idx < 64 * 128; idx += 512) {
        int r = idx >> 7; int k4 = (idx & 127) << 2;
        int q = r & 3, w = r >> 2;
        int grow = q * HH + col_base + w;
        float4 v = *(const float4*)(w_hh + (size_t)grow * HH + k4);
        float* d = w_sm + r * LWP + k4;
        d[0] = v.x; d[1] = v.y; d[2] = v.z; d[3] = v.w;
    }

    const int w    = tid >> 5;        // warp 0..15 -> column
    const int lane = tid & 31;
    const int q    = lane >> 3;       // gate 0..3 (i,f,g,o)
    const int b    = lane & 7;        // batch within group
    const int col  = col_base + w;
    const int batch = b_base + b;
    const int xgcol = q * HH + col;
    const float* wrow = w_sm + (w * 4 + q) * LWP;
    const float* hrow = h_sm + b * LHP;
    const size_t xgbase = (size_t)(batch * TT) * (4 * HH) + xgcol;
    float c_reg = 0.f;

    __syncthreads();   // w_sm ready; h_sm safe to write

    for (int t = 0; t < TT; t++) {
        const float* hprev = (t & 1) ? hbuf1 : hbuf0;
        float*       hnext = (t & 1) ? hbuf0 : hbuf1;

        // wait for group's step-(t-1) h to be published
        if (t > 0) {
            if (tid < 32) {
                const unsigned* fp = &g_flags[(group * 32 + tid) * 32];
                unsigned v;
                do {
                    asm volatile("ld.acquire.gpu.global.u32 %0, [%1];"
                                 : "=r"(v) : "l"(fp) : "memory");
                } while (v < (unsigned)t);
            }
            __syncthreads();   // all h_sm readers of step t-1 also done
        }

        // stage this group's h slice [8, 512] -> smem (16 KB)
        #pragma unroll
        for (int i = 0; i < 2; i++) {
            int idx = tid + i * 512;          // 0..1023
            int row = idx >> 7; int k4 = (idx & 127) << 2;
            cp_async16(h_sm + row * LHP + k4, hprev + (b_base + row) * HH + k4);
        }
        cp_async_commit();

        float xgv = __ldg(xg + xgbase + (size_t)t * (4 * HH));

        CP_WAIT(0);
        __syncthreads();

        // gate pre-activation: dot(w_row, h_row), 2 chains
        float a0 = 0.f, a1 = 0.f;
        #pragma unroll 8
        for (int k = 0; k < HH; k += 8) {
            float4 w0 = *(const float4*)(wrow + k);
            float4 w1 = *(const float4*)(wrow + k + 4);
            float4 h0 = *(const float4*)(hrow + k);
            float4 h1 = *(const float4*)(hrow + k + 4);
            a0 = fmaf(w0.x, h0.x, a0); a1 = fmaf(w1.x, h1.x, a1);
            a0 = fmaf(w0.y, h0.y, a0); a1 = fmaf(w1.y, h1.y, a1);
            a0 = fmaf(w0.z, h0.z, a0); a1 = fmaf(w1.z, h1.z, a1);
            a0 = fmaf(w0.w, h0.w, a0); a1 = fmaf(w1.w, h1.w, a1);
        }
        float gate = a0 + a1 + xgv;

        // gather f,g,o from lanes +8,+16,+24 (same batch, gates 1..3)
        float fv = __shfl_down_sync(0xffffffffu, gate, 8);
        float gv = __shfl_down_sync(0xffffffffu, gate, 16);
        float ov = __shfl_down_sync(0xffffffffu, gate, 24);

        if (q == 0) {
            float ig = 1.f / (1.f + __expf(-gate));
            float fg = 1.f / (1.f + __expf(-fv));
            float og = 1.f / (1.f + __expf(-ov));
            float gg = tanhf(gv);
            c_reg = fg * c_reg + ig * gg;
            float hn = og * tanhf(c_reg);
            __stcg(hnext + batch * HH + col, hn);
            __stcg(lstm_out + (size_t)(batch * TT + t) * HH + col, hn);
            __threadfence();
        }
        __syncthreads();

        // publish: this block's step-t h is visible
        if (tid == 0) {
            asm volatile("st.release.gpu.global.u32 [%0], %1;"
                         :: "l"(&g_flags[blockIdx.x * 32]), "r"((unsigned)(t + 1)) : "memory");
        }
    }
}

// ---------------- fused attention: per (t-chunk, head, batch) ----------------
#define KTP 257   // transposed K/V pitch (257 mod 32 == 1 -> conflict-free lane stride)
#define QSP 68
#define PSP 260
__global__ __launch_bounds__(256) void attn_kernel(
    const float* __restrict__ q, const float* __restrict__ kmat,
    const float* __restrict__ vmat, float* __restrict__ ctx)
{
    extern __shared__ float smem[];
    float* Kt   = smem;                    // [64][KTP]
    float* Vt   = Kt + 64 * KTP;           // [64][KTP]
    float* qs   = Vt + 64 * KTP;           // [32][QSP]
    float* ps   = qs + 32 * QSP;           // [32][PSP]
    float* sums = ps + 32 * PSP;           // [32]

    const int t0 = blockIdx.x * 32;
    const int h  = blockIdx.y;
    const int b  = blockIdx.z;
    const int tid = threadIdx.x;

    // load K,V transposed: Kt[d][s] = K[b*256+s][h*64+d]
    for (int idx = tid; idx < 256 * 16; idx += 256) {
        int s = idx >> 4; int d4 = (idx & 15) << 2;
        size_t off = (size_t)(b * SS + s) * HH + h * HDD + d4;
        float4 kv = *(const float4*)(kmat + off);
        Kt[(d4 + 0) * KTP + s] = kv.x; Kt[(d4 + 1) * KTP + s] = kv.y;
        Kt[(d4 + 2) * KTP + s] = kv.z; Kt[(d4 + 3) * KTP + s] = kv.w;
        float4 vv = *(const float4*)(vmat + off);
        Vt[(d4 + 0) * KTP + s] = vv.x; Vt[(d4 + 1) * KTP + s] = vv.y;
        Vt[(d4 + 2) * KTP + s] = vv.z; Vt[(d4 + 3) * KTP + s] = vv.w;
    }
    // load q chunk
    for (int idx = tid; idx < 32 * 16; idx += 256) {
        int r = idx >> 4; int d4 = (idx & 15) << 2;
        int trow = t0 + r;
        float4 qv = make_float4(0.f, 0.f, 0.f, 0.f);
        if (trow < TT)
            qv = *(const float4*)(q + (size_t)(b * TT + trow) * HH + h * HDD + d4);
        float* d = qs + r * QSP + d4;
        d[0] = qv.x; d[1] = qv.y; d[2] = qv.z; d[3] = qv.w;
    }
    __syncthreads();

    const int r  = tid >> 3;  // query row in chunk
    const int lc = tid & 7;   // lane-col

    float qreg[64];
    #pragma unroll
    for (int d = 0; d < 64; d++) qreg[d] = qs[r * QSP + d];

    float sc[32];
    for (int si = 0; si < 32; si++) {
        int s = si * 8 + lc;
        float acc = 0.f;
        #pragma unroll
        for (int d = 0; d < 64; d++) acc += qreg[d] * Kt[d * KTP + s];
        sc[si] = acc * 0.125f;   // 1/sqrt(64)
    }
    float m = -1e30f;
    #pragma unroll
    for (int si = 0; si < 32; si++) m = fmaxf(m, sc[si]);
    m = fmaxf(m, __shfl_xor_sync(0xffffffff, m, 1));
    m = fmaxf(m, __shfl_xor_sync(0xffffffff, m, 2));
    m = fmaxf(m, __shfl_xor_sync(0xffffffff, m, 4));
    float ssum = 0.f;
    #pragma unroll
    for (int si = 0; si < 32; si++) {
        float e = __expf(sc[si] - m);
        ssum += e;
        ps[r * PSP + si * 8 + lc] = e;
    }
    ssum += __shfl_xor_sync(0xffffffff, ssum, 1);
    ssum += __shfl_xor_sync(0xffffffff, ssum, 2);
    ssum += __shfl_xor_sync(0xffffffff, ssum, 4);
    if (lc == 0) sums[r] = ssum;
    __syncthreads();

    // ctx: thread covers d = lc + 8j
    float accv[8];
    #pragma unroll
    for (int j = 0; j < 8; j++) accv[j] = 0.f;
    const float* prow = ps + r * PSP;
    #pragma unroll 4
    for (int s = 0; s < 256; s++) {
        float pv = prow[s];
        #pragma unroll
        for (int j = 0; j < 8; j++)
            accv[j] += pv * Vt[(lc + 8 * j) * KTP + s];
    }
    float inv = 1.0f / sums[r];
    int trow = t0 + r;
    if (trow < TT) {
        float* dst = ctx + (size_t)(b * TT + trow) * HH + h * HDD;
        #pragma unroll
        for (int j = 0; j < 8; j++) dst[lc + 8 * j] = accv[j] * inv;
    }
}

// ---------------- launch ----------------
extern "C" void kernel_launch(void* const* d_in, const int* in_sizes, int n_in,
                              void* d_out, int out_size) {
    const int*   targets  = (const int*)  d_in[0];
    const float* enc      = (const float*)d_in[1];
    const float* embedding= (const float*)d_in[2];
    const float* w_ih     = (const float*)d_in[3];
    const float* w_hh     = (const float*)d_in[4];
    const float* b_ih     = (const float*)d_in[5];
    const float* b_hh     = (const float*)d_in[6];
    const float* in_proj_w= (const float*)d_in[7];
    const float* in_proj_b= (const float*)d_in[8];
    const float* out_proj_w=(const float*)d_in[9];
    const float* out_proj_b=(const float*)d_in[10];
    const float* fc_w     = (const float*)d_in[11];
    const float* fc_b     = (const float*)d_in[12];
    float* out = (float*)d_out;

    float *p_emb, *p_xg, *p_h, *p_lstm, *p_q, *p_k, *p_v, *p_ctx, *p_comb;
    cudaGetSymbolAddress((void**)&p_emb,  g_emb);
    cudaGetSymbolAddress((void**)&p_xg,   g_xg);
    cudaGetSymbolAddress((void**)&p_h,    g_h);
    cudaGetSymbolAddress((void**)&p_lstm, g_lstm);
    cudaGetSymbolAddress((void**)&p_q,    g_q);
    cudaGetSymbolAddress((void**)&p_k,    g_k);
    cudaGetSymbolAddress((void**)&p_v,    g_v);
    cudaGetSymbolAddress((void**)&p_ctx,  g_ctx);
    cudaGetSymbolAddress((void**)&p_comb, g_comb);
    float* h_buf0 = p_h;
    float* h_buf1 = p_h + BB * HH;

    const int lstm_smem = (8 * LHP + 64 * LWP) * (int)sizeof(float);   // ~149 KB
    const int attn_smem = (64 * KTP * 2 + 32 * QSP + 32 * PSP + 32) * (int)sizeof(float);
    cudaFuncSetAttribute(lstm_persistent_kernel, cudaFuncAttributeMaxDynamicSharedMemorySize, lstm_smem);
    cudaFuncSetAttribute(attn_kernel,            cudaFuncAttributeMaxDynamicSharedMemorySize, attn_smem);

    // 1. zero h0 + flags
    zero_kernel<<<(BB * HH + 255) / 256, 256>>>(h_buf0, BB * HH);

    // 2. gather embeddings
    gather_kernel<<<BT, 128>>>(targets, embedding, p_emb);

    // 3. xg = emb @ w_ih^T + b_ih + b_hh   [4064, 2048]
    {
        dim3 grid((4 * HH + 127) / 128, (BT + 127) / 128);
        sgemm_kernel<<<grid, 256>>>(p_emb, w_ih, b_ih, b_hh, nullptr, p_xg, BT, 4 * HH, HH);
    }

    // 4. LSTM recurrence — one persistent kernel, 4 independent batch groups
    lstm_persistent_kernel<<<NBLK, 512, lstm_smem>>>(p_xg, w_hh, h_buf0, h_buf1, p_lstm);

    // 5. q/k/v projections
    {
        dim3 gq((HH + 127) / 128, (BT + 127) / 128);
        sgemm_kernel<<<gq, 256>>>(p_lstm, in_proj_w, in_proj_b, nullptr, nullptr, p_q, BT, HH, HH);
        dim3 gk((HH + 127) / 128, (BS + 127) / 128);
        sgemm_kernel<<<gk, 256>>>(enc, in_proj_w + (size_t)HH * HH, in_proj_b + HH,
                                  nullptr, nullptr, p_k, BS, HH, HH);
        sgemm_kernel<<<gk, 256>>>(enc, in_proj_w + (size_t)2 * HH * HH, in_proj_b + 2 * HH,
                                  nullptr, nullptr, p_v, BS, HH, HH);
    }

    // 6. fused attention -> ctx
    {
        dim3 grid(4, NHH, BB);
        attn_kernel<<<grid, 256, attn_smem>>>(p_q, p_k, p_v, p_ctx);
    }

    // 7. combined = ctx @ out_proj^T + out_proj_b + lstm_out
    {
        dim3 grid((HH + 127) / 128, (BT + 127) / 128);
        sgemm_kernel<<<grid, 256>>>(p_ctx, out_proj_w, out_proj_b, nullptr, p_lstm, p_comb, BT, HH, HH);
    }

    // 8. out = combined @ fc_w^T + fc_b   [4064, 8000]
    {
        dim3 grid((VV + 127) / 128, (BT + 127) / 128);
        sgemm_kernel<<<grid, 256>>>(p_comb, fc_w, fc_b, nullptr, nullptr, out, BT, VV, HH);
    }
}

// round 6
// speedup vs baseline: 1.0800x; 1.0504x over previous
#include <cuda_runtime.h>
#include <cuda_bf16.h>
#include <math.h>

// Problem constants
#define BB   32
#define TT   127
#define SS   256
#define HH   512
#define VV   8000
#define NHH  8
#define HDD  64
#define BT   (BB*TT)      // 4064
#define BS   (BB*SS)      // 8192
#define NBLK 128          // persistent LSTM grid (4 groups x 32 blocks)

// ---------------- scratch (device globals; no allocations allowed) ----------------
__device__ float g_emb [BT * HH];        // embedded targets
__device__ float g_xg  [BT * 4 * HH];    // precomputed input gates
__device__ float g_h   [2][BB * HH];     // ping-pong hidden state
__device__ float g_lstm[BT * HH];        // lstm outputs
__device__ float g_q   [BT * HH];
__device__ float g_k   [BS * HH];
__device__ float g_v   [BS * HH];
__device__ float g_ctx [BT * HH];
__device__ float g_comb[BT * HH];
__device__ unsigned g_flags[NBLK * 2 * 32];  // per (block, half) step flags, 128B padded

// ---------------- cp.async helpers ----------------
__device__ __forceinline__ void cp_async16(float* dst_smem, const float* src_gmem) {
    unsigned s = (unsigned)__cvta_generic_to_shared(dst_smem);
    asm volatile("cp.async.cg.shared.global [%0], [%1], 16;\n" :: "r"(s), "l"(src_gmem));
}
__device__ __forceinline__ void cp_async_commit() { asm volatile("cp.async.commit_group;\n"); }
#define CP_WAIT0() asm volatile("cp.async.wait_group 0;\n")

// ---------------- init: zero h0 and flags ----------------
__global__ void zero_kernel(float* h0, int n) {
    int i = blockIdx.x * blockDim.x + threadIdx.x;
    if (i < n) h0[i] = 0.f;
    if (i < NBLK * 2 * 32) g_flags[i] = 0u;
}

// ---------------- embedding gather ----------------
__global__ void gather_kernel(const int* __restrict__ targets,
                              const float* __restrict__ table,
                              float* __restrict__ out) {
    int bt = blockIdx.x;                 // 0..4063
    int b = bt / TT, t = bt - b * TT;
    int tok = targets[b * 128 + t];      // targets is [B,128], use [:, :-1]
    const float4* src = (const float4*)(table + (size_t)tok * HH);
    float4* dst = (float4*)(out + (size_t)bt * HH);
    dst[threadIdx.x] = src[threadIdx.x]; // 128 threads * float4 = 512 floats
}

// ---------------- generic SGEMM: C[M,N] = A[M,K] @ B[N,K]^T + bias1 + bias2 + res ----------------
__global__ __launch_bounds__(256) void sgemm_kernel(
    const float* __restrict__ A, const float* __restrict__ B,
    const float* __restrict__ bias1, const float* __restrict__ bias2,
    const float* __restrict__ res, float* __restrict__ C,
    int M, int N, int K)
{
    __shared__ float As[8][128];
    __shared__ float Bs[8][128];
    const int bm = blockIdx.y * 128;
    const int bn = blockIdx.x * 128;
    const int tid = threadIdx.x;
    const int lr = tid >> 1;            // 0..127 (load row)
    const int lc = (tid & 1) << 2;      // 0 or 4 (load col group)
    const int tx = tid & 15;            // n-tile
    const int ty = tid >> 4;            // m-tile

    float acc[8][8];
    #pragma unroll
    for (int i = 0; i < 8; i++)
        #pragma unroll
        for (int j = 0; j < 8; j++) acc[i][j] = 0.f;

    const bool aval = (bm + lr) < M;
    const bool bval = (bn + lr) < N;
    const float* Aptr = A + (size_t)(bm + lr) * K + lc;
    const float* Bptr = B + (size_t)(bn + lr) * K + lc;
    const float4 zero4 = make_float4(0.f, 0.f, 0.f, 0.f);

    for (int k0 = 0; k0 < K; k0 += 8) {
        float4 a4 = aval ? *(const float4*)(Aptr + k0) : zero4;
        float4 b4 = bval ? *(const float4*)(Bptr + k0) : zero4;
        As[lc + 0][lr] = a4.x; As[lc + 1][lr] = a4.y;
        As[lc + 2][lr] = a4.z; As[lc + 3][lr] = a4.w;
        Bs[lc + 0][lr] = b4.x; Bs[lc + 1][lr] = b4.y;
        Bs[lc + 2][lr] = b4.z; Bs[lc + 3][lr] = b4.w;
        __syncthreads();
        #pragma unroll
        for (int kk = 0; kk < 8; kk++) {
            float ra[8], rb[8];
            *(float4*)(ra)     = *(const float4*)(&As[kk][ty * 8]);
            *(float4*)(ra + 4) = *(const float4*)(&As[kk][ty * 8 + 4]);
            *(float4*)(rb)     = *(const float4*)(&Bs[kk][tx * 8]);
            *(float4*)(rb + 4) = *(const float4*)(&Bs[kk][tx * 8 + 4]);
            #pragma unroll
            for (int i = 0; i < 8; i++)
                #pragma unroll
                for (int j = 0; j < 8; j++)
                    acc[i][j] += ra[i] * rb[j];
        }
        __syncthreads();
    }

    #pragma unroll
    for (int i = 0; i < 8; i++) {
        int row = bm + ty * 8 + i;
        if (row >= M) continue;
        #pragma unroll
        for (int j = 0; j < 8; j++) {
            int col = bn + tx * 8 + j;
            if (col >= N) continue;
            float v = acc[i][j];
            if (bias1) v += bias1[col];
            if (bias2) v += bias2[col];
            if (res)   v += res[(size_t)row * N + col];
            C[(size_t)row * N + col] = v;
        }
    }
}

// ---------------- persistent LSTM: 4 groups x 32 blocks x 512 threads, 2 pipelines/block ----
// Group g owns batches [8g, 8g+8). Block slot s owns columns [16s, 16s+16) -> 64 gate rows
// (132KB fp32 weights in smem, loaded once, shared by both halves).
// Half A = warps 0-7 handles batches [8g, 8g+4); half B = warps 8-15 handles [8g+4, 8g+8).
// Halves run fully independent step pipelines (own flags, own named barrier, own h stage),
// overlapping each other's sync/staging latency on the SM.
// Thread map within half: t8 = tid&255: colL = t8>>4 (16 cols), gate = (t8>>2)&3, b4 = t8&3.
#define LWP 516   // w smem pitch (rows stride 4 banks apart)
#define LHP 516   // h smem pitch
__global__ __launch_bounds__(512) void lstm_persistent_kernel(
    const float* __restrict__ xg, const float* __restrict__ w_hh,
    float* __restrict__ hbuf0, float* __restrict__ hbuf1,
    float* __restrict__ lstm_out)
{
    extern __shared__ float smem[];
    float* w_sm  = smem;                     // 64 * LWP
    float* h_smA = smem + 64 * LWP;          // 4 * LHP
    float* h_smB = h_smA + 4 * LHP;          // 4 * LHP

    const int tid   = threadIdx.x;
    const int group = blockIdx.x >> 5;       // 0..3
    const int gslot = blockIdx.x & 31;       // 0..31
    const int col_base = gslot * 16;

    // Load 64 w_hh rows once: smem row r = colL*4 + q  <-  w_hh[q*512 + col_base + colL]
    for (int idx = tid; idx < 64 * 128; idx += 512) {
        int r = idx >> 7; int k4 = (idx & 127) << 2;
        int colL = r >> 2, q = r & 3;
        float4 v = *(const float4*)(w_hh + (size_t)(q * HH + col_base + colL) * HH + k4);
        float* d = w_sm + r * LWP + k4;
        d[0] = v.x; d[1] = v.y; d[2] = v.z; d[3] = v.w;
    }

    const int half = tid >> 8;               // 0 or 1
    const int t8   = tid & 255;
    const int colL = t8 >> 4;                // 0..15
    const int gate = (t8 >> 2) & 3;          // 0..3 (i,f,g,o)
    const int b4   = t8 & 3;                 // 0..3
    const int gcol  = col_base + colL;
    const int batch = group * 8 + half * 4 + b4;
    float* h_sm = half ? h_smB : h_smA;
    const float* wrow = w_sm + (colL * 4 + gate) * LWP;
    const float* hrow = h_sm + b4 * LHP;
    const size_t xgbase = (size_t)(batch * TT) * (4 * HH) + gate * HH + gcol;
    const int bar_id = 1 + half;
    const int b_base = group * 8 + half * 4;
    // flag for (block, half); poll set = 32 group peers, same half
    unsigned* my_flag = &g_flags[(blockIdx.x * 2 + half) * 32];
    float c_reg = 0.f;

    __syncthreads();   // w_sm ready, h_sm safe

    for (int t = 0; t < TT; t++) {
        const float* hprev = (t & 1) ? hbuf1 : hbuf0;
        float*       hnext = (t & 1) ? hbuf0 : hbuf1;

        if (t > 0) {
            // wait for this half's group peers to publish step t-1 h
            if (t8 < 32) {
                const unsigned* fp = &g_flags[((group * 32 + t8) * 2 + half) * 32];
                unsigned v;
                do {
                    asm volatile("ld.acquire.gpu.global.u32 %0, [%1];"
                                 : "=r"(v) : "l"(fp) : "memory");
                } while (v < (unsigned)t);
            }
            asm volatile("bar.sync %0, %1;" :: "r"(bar_id), "r"(256) : "memory");
        }

        // stage this half's h slice [4, 512] -> smem (8 KB); 2 float4 per thread
        #pragma unroll
        for (int i = 0; i < 2; i++) {
            int idx = t8 + i * 256;              // 0..511
            int row = idx >> 7; int k4 = (idx & 127) << 2;
            cp_async16(h_sm + row * LHP + k4, hprev + (b_base + row) * HH + k4);
        }
        cp_async_commit();

        float xgv = __ldg(xg + xgbase + (size_t)t * (4 * HH));

        CP_WAIT0();
        asm volatile("bar.sync %0, %1;" :: "r"(bar_id), "r"(256) : "memory");

        // gate pre-activation: dot(wrow, hrow) over 512, 4 accumulator chains
        float a0 = 0.f, a1 = 0.f, a2 = 0.f, a3 = 0.f;
        #pragma unroll
        for (int k = 0; k < HH; k += 16) {
            float4 w0 = *(const float4*)(wrow + k);
            float4 w1 = *(const float4*)(wrow + k + 4);
            float4 w2 = *(const float4*)(wrow + k + 8);
            float4 w3 = *(const float4*)(wrow + k + 12);
            float4 h0 = *(const float4*)(hrow + k);
            float4 h1 = *(const float4*)(hrow + k + 4);
            float4 h2 = *(const float4*)(hrow + k + 8);
            float4 h3 = *(const float4*)(hrow + k + 12);
            a0 = fmaf(w0.x, h0.x, a0); a1 = fmaf(w1.x, h1.x, a1);
            a2 = fmaf(w2.x, h2.x, a2); a3 = fmaf(w3.x, h3.x, a3);
            a0 = fmaf(w0.y, h0.y, a0); a1 = fmaf(w1.y, h1.y, a1);
            a2 = fmaf(w2.y, h2.y, a2); a3 = fmaf(w3.y, h3.y, a3);
            a0 = fmaf(w0.z, h0.z, a0); a1 = fmaf(w1.z, h1.z, a1);
            a2 = fmaf(w2.z, h2.z, a2); a3 = fmaf(w3.z, h3.z, a3);
            a0 = fmaf(w0.w, h0.w, a0); a1 = fmaf(w1.w, h1.w, a1);
            a2 = fmaf(w2.w, h2.w, a2); a3 = fmaf(w3.w, h3.w, a3);
        }
        float gatev = (a0 + a1) + (a2 + a3) + xgv;

        // gather f,g,o from lanes +4,+8,+12 (same col, same batch; within 16-lane subgroup)
        float fv = __shfl_down_sync(0xffffffffu, gatev, 4);
        float gv = __shfl_down_sync(0xffffffffu, gatev, 8);
        float ov = __shfl_down_sync(0xffffffffu, gatev, 12);

        if (gate == 0) {
            float ig = 1.f / (1.f + __expf(-gatev));
            float fg = 1.f / (1.f + __expf(-fv));
            float og = 1.f / (1.f + __expf(-ov));
            float gg = tanhf(gv);
            c_reg = fg * c_reg + ig * gg;
            float hn = og * tanhf(c_reg);
            __stcg(hnext + batch * HH + gcol, hn);
            __stcg(lstm_out + (size_t)(batch * TT + t) * HH + gcol, hn);
        }
        asm volatile("bar.sync %0, %1;" :: "r"(bar_id), "r"(256) : "memory");

        // publish (single fence + release store per half; bar orders peers' writes into it)
        if (t8 == 0) {
            asm volatile("fence.acq_rel.gpu;" ::: "memory");
            asm volatile("st.release.gpu.global.u32 [%0], %1;"
                         :: "l"(my_flag), "r"((unsigned)(t + 1)) : "memory");
        }
    }
}

// ---------------- fused attention: per (t-chunk, head, batch) ----------------
#define KTP 257   // transposed K/V pitch (257 mod 32 == 1 -> conflict-free lane stride)
#define QSP 68
#define PSP 260
__global__ __launch_bounds__(256) void attn_kernel(
    const float* __restrict__ q, const float* __restrict__ kmat,
    const float* __restrict__ vmat, float* __restrict__ ctx)
{
    extern __shared__ float smem[];
    float* Kt   = smem;                    // [64][KTP]
    float* Vt   = Kt + 64 * KTP;           // [64][KTP]
    float* qs   = Vt + 64 * KTP;           // [32][QSP]
    float* ps   = qs + 32 * QSP;           // [32][PSP]
    float* sums = ps + 32 * PSP;           // [32]

    const int t0 = blockIdx.x * 32;
    const int h  = blockIdx.y;
    const int b  = blockIdx.z;
    const int tid = threadIdx.x;

    // load K,V transposed: Kt[d][s] = K[b*256+s][h*64+d]
    for (int idx = tid; idx < 256 * 16; idx += 256) {
        int s = idx >> 4; int d4 = (idx & 15) << 2;
        size_t off = (size_t)(b * SS + s) * HH + h * HDD + d4;
        float4 kv = *(const float4*)(kmat + off);
        Kt[(d4 + 0) * KTP + s] = kv.x; Kt[(d4 + 1) * KTP + s] = kv.y;
        Kt[(d4 + 2) * KTP + s] = kv.z; Kt[(d4 + 3) * KTP + s] = kv.w;
        float4 vv = *(const float4*)(vmat + off);
        Vt[(d4 + 0) * KTP + s] = vv.x; Vt[(d4 + 1) * KTP + s] = vv.y;
        Vt[(d4 + 2) * KTP + s] = vv.z; Vt[(d4 + 3) * KTP + s] = vv.w;
    }
    // load q chunk
    for (int idx = tid; idx < 32 * 16; idx += 256) {
        int r = idx >> 4; int d4 = (idx & 15) << 2;
        int trow = t0 + r;
        float4 qv = make_float4(0.f, 0.f, 0.f, 0.f);
        if (trow < TT)
            qv = *(const float4*)(q + (size_t)(b * TT + trow) * HH + h * HDD + d4);
        float* d = qs + r * QSP + d4;
        d[0] = qv.x; d[1] = qv.y; d[2] = qv.z; d[3] = qv.w;
    }
    __syncthreads();

    const int r  = tid >> 3;  // query row in chunk
    const int lc = tid & 7;   // lane-col

    float qreg[64];
    #pragma unroll
    for (int d = 0; d < 64; d++) qreg[d] = qs[r * QSP + d];

    float sc[32];
    for (int si = 0; si < 32; si++) {
        int s = si * 8 + lc;
        float acc = 0.f;
        #pragma unroll
        for (int d = 0; d < 64; d++) acc += qreg[d] * Kt[d * KTP + s];
        sc[si] = acc * 0.125f;   // 1/sqrt(64)
    }
    float m = -1e30f;
    #pragma unroll
    for (int si = 0; si < 32; si++) m = fmaxf(m, sc[si]);
    m = fmaxf(m, __shfl_xor_sync(0xffffffff, m, 1));
    m = fmaxf(m, __shfl_xor_sync(0xffffffff, m, 2));
    m = fmaxf(m, __shfl_xor_sync(0xffffffff, m, 4));
    float ssum = 0.f;
    #pragma unroll
    for (int si = 0; si < 32; si++) {
        float e = __expf(sc[si] - m);
        ssum += e;
        ps[r * PSP + si * 8 + lc] = e;
    }
    ssum += __shfl_xor_sync(0xffffffff, ssum, 1);
    ssum += __shfl_xor_sync(0xffffffff, ssum, 2);
    ssum += __shfl_xor_sync(0xffffffff, ssum, 4);
    if (lc == 0) sums[r] = ssum;
    __syncthreads();

    // ctx: thread covers d = lc + 8j
    float accv[8];
    #pragma unroll
    for (int j = 0; j < 8; j++) accv[j] = 0.f;
    const float* prow = ps + r * PSP;
    #pragma unroll 4
    for (int s = 0; s < 256; s++) {
        float pv = prow[s];
        #pragma unroll
        for (int j = 0; j < 8; j++)
            accv[j] += pv * Vt[(lc + 8 * j) * KTP + s];
    }
    float inv = 1.0f / sums[r];
    int trow = t0 + r;
    if (trow < TT) {
        float* dst = ctx + (size_t)(b * TT + trow) * HH + h * HDD;
        #pragma unroll
        for (int j = 0; j < 8; j++) dst[lc + 8 * j] = accv[j] * inv;
    }
}

// ---------------- launch ----------------
extern "C" void kernel_launch(void* const* d_in, const int* in_sizes, int n_in,
                              void* d_out, int out_size) {
    const int*   targets  = (const int*)  d_in[0];
    const float* enc      = (const float*)d_in[1];
    const float* embedding= (const float*)d_in[2];
    const float* w_ih     = (const float*)d_in[3];
    const float* w_hh     = (const float*)d_in[4];
    const float* b_ih     = (const float*)d_in[5];
    const float* b_hh     = (const float*)d_in[6];
    const float* in_proj_w= (const float*)d_in[7];
    const float* in_proj_b= (const float*)d_in[8];
    const float* out_proj_w=(const float*)d_in[9];
    const float* out_proj_b=(const float*)d_in[10];
    const float* fc_w     = (const float*)d_in[11];
    const float* fc_b     = (const float*)d_in[12];
    float* out = (float*)d_out;

    float *p_emb, *p_xg, *p_h, *p_lstm, *p_q, *p_k, *p_v, *p_ctx, *p_comb;
    cudaGetSymbolAddress((void**)&p_emb,  g_emb);
    cudaGetSymbolAddress((void**)&p_xg,   g_xg);
    cudaGetSymbolAddress((void**)&p_h,    g_h);
    cudaGetSymbolAddress((void**)&p_lstm, g_lstm);
    cudaGetSymbolAddress((void**)&p_q,    g_q);
    cudaGetSymbolAddress((void**)&p_k,    g_k);
    cudaGetSymbolAddress((void**)&p_v,    g_v);
    cudaGetSymbolAddress((void**)&p_ctx,  g_ctx);
    cudaGetSymbolAddress((void**)&p_comb, g_comb);
    float* h_buf0 = p_h;
    float* h_buf1 = p_h + BB * HH;

    const int lstm_smem = (64 * LWP + 8 * LHP) * (int)sizeof(float);   // ~145 KB
    const int attn_smem = (64 * KTP * 2 + 32 * QSP + 32 * PSP + 32) * (int)sizeof(float);
    cudaFuncSetAttribute(lstm_persistent_kernel, cudaFuncAttributeMaxDynamicSharedMemorySize, lstm_smem);
    cudaFuncSetAttribute(attn_kernel,            cudaFuncAttributeMaxDynamicSharedMemorySize, attn_smem);

    // 1. zero h0 + flags
    zero_kernel<<<(BB * HH + 255) / 256, 256>>>(h_buf0, BB * HH);

    // 2. gather embeddings
    gather_kernel<<<BT, 128>>>(targets, embedding, p_emb);

    // 3. xg = emb @ w_ih^T + b_ih + b_hh   [4064, 2048]
    {
        dim3 grid((4 * HH + 127) / 128, (BT + 127) / 128);
        sgemm_kernel<<<grid, 256>>>(p_emb, w_ih, b_ih, b_hh, nullptr, p_xg, BT, 4 * HH, HH);
    }

    // 4. LSTM recurrence — one persistent kernel, dual pipelines per block
    lstm_persistent_kernel<<<NBLK, 512, lstm_smem>>>(p_xg, w_hh, h_buf0, h_buf1, p_lstm);

    // 5. q/k/v projections
    {
        dim3 gq((HH + 127) / 128, (BT + 127) / 128);
        sgemm_kernel<<<gq, 256>>>(p_lstm, in_proj_w, in_proj_b, nullptr, nullptr, p_q, BT, HH, HH);
        dim3 gk((HH + 127) / 128, (BS + 127) / 128);
        sgemm_kernel<<<gk, 256>>>(enc, in_proj_w + (size_t)HH * HH, in_proj_b + HH,
                                  nullptr, nullptr, p_k, BS, HH, HH);
        sgemm_kernel<<<gk, 256>>>(enc, in_proj_w + (size_t)2 * HH * HH, in_proj_b + 2 * HH,
                                  nullptr, nullptr, p_v, BS, HH, HH);
    }

    // 6. fused attention -> ctx
    {
        dim3 grid(4, NHH, BB);
        attn_kernel<<<grid, 256, attn_smem>>>(p_q, p_k, p_v, p_ctx);
    }

    // 7. combined = ctx @ out_proj^T + out_proj_b + lstm_out
    {
        dim3 grid((HH + 127) / 128, (BT + 127) / 128);
        sgemm_kernel<<<grid, 256>>>(p_ctx, out_proj_w, out_proj_b, nullptr, p_lstm, p_comb, BT, HH, HH);
    }

    // 8. out = combined @ fc_w^T + fc_b   [4064, 8000]
    {
        dim3 grid((VV + 127) / 128, (BT + 127) / 128);
        sgemm_kernel<<<grid, 256>>>(p_comb, fc_w, fc_b, nullptr, nullptr, out, BT, VV, HH);
    }
}

// round 8
// speedup vs baseline: 1.1234x; 1.0401x over previous
#include <cuda_runtime.h>
#include <cuda_bf16.h>
#include <math.h>

// Problem constants
#define BB   32
#define TT   127
#define SS   256
#define HH   512
#define VV   8000
#define NHH  8
#define HDD  64
#define BT   (BB*TT)      // 4064
#define BS   (BB*SS)      // 8192
#define NBLK 128          // persistent LSTM grid (4 groups x 32 blocks)

// ---------------- scratch (device globals; no allocations allowed) ----------------
__device__ float g_emb [BT * HH];        // embedded targets
__device__ float g_xg  [BT * 4 * HH];    // precomputed input gates
__device__ float g_h   [2][BB * HH];     // ping-pong hidden state
__device__ float g_lstm[BT * HH];        // lstm outputs
__device__ float g_q   [BT * HH];
__device__ float g_k   [BS * HH];
__device__ float g_v   [BS * HH];
__device__ float g_ctx [BT * HH];
__device__ float g_comb[BT * HH];
__device__ unsigned g_flags[NBLK * 2 * 32];  // per (block, half) step flags, 128B padded

// ---------------- cp.async helpers ----------------
__device__ __forceinline__ void cp_async16(float* dst_smem, const float* src_gmem) {
    unsigned s = (unsigned)__cvta_generic_to_shared(dst_smem);
    asm volatile("cp.async.cg.shared.global [%0], [%1], 16;\n" :: "r"(s), "l"(src_gmem));
}
__device__ __forceinline__ void cp_async_commit() { asm volatile("cp.async.commit_group;\n"); }
#define CP_WAIT0() asm volatile("cp.async.wait_group 0;\n")

// ---------------- init: zero h0 and flags ----------------
__global__ void zero_kernel(float* h0, int n) {
    int i = blockIdx.x * blockDim.x + threadIdx.x;
    if (i < n) h0[i] = 0.f;
    if (i < NBLK * 2 * 32) g_flags[i] = 0u;
}

// ---------------- embedding gather ----------------
__global__ void gather_kernel(const int* __restrict__ targets,
                              const float* __restrict__ table,
                              float* __restrict__ out) {
    int bt = blockIdx.x;                 // 0..4063
    int b = bt / TT, t = bt - b * TT;
    int tok = targets[b * 128 + t];      // targets is [B,128], use [:, :-1]
    const float4* src = (const float4*)(table + (size_t)tok * HH);
    float4* dst = (float4*)(out + (size_t)bt * HH);
    dst[threadIdx.x] = src[threadIdx.x]; // 128 threads * float4 = 512 floats
}

// ---------------- SGEMM: C[M,N] = A[M,K] @ B[N,K]^T + bias1 + bias2 + res ----------------
// Double-buffered smem + register prefetch: LDG of chunk k+1 overlaps FMA of chunk k.
// One __syncthreads per 8-deep K-chunk. Vectorized epilogue (requires N % 4 == 0,
// true for all call sites: 2048, 512, 8000).
__global__ __launch_bounds__(256) void sgemm_kernel(
    const float* __restrict__ A, const float* __restrict__ B,
    const float* __restrict__ bias1, const float* __restrict__ bias2,
    const float* __restrict__ res, float* __restrict__ C,
    int M, int N, int K)
{
    __shared__ float As[2][8][132];
    __shared__ float Bs[2][8][132];
    const int bm = blockIdx.y * 128;
    const int bn = blockIdx.x * 128;
    const int tid = threadIdx.x;
    const int lr = tid >> 1;            // 0..127 (load row)
    const int lc = (tid & 1) << 2;      // 0 or 4 (load col group)
    const int tx = tid & 15;            // n-tile
    const int ty = tid >> 4;            // m-tile

    float acc[8][8];
    #pragma unroll
    for (int i = 0; i < 8; i++)
        #pragma unroll
        for (int j = 0; j < 8; j++) acc[i][j] = 0.f;

    const bool aval = (bm + lr) < M;
    const bool bval = (bn + lr) < N;
    const float* Aptr = A + (size_t)(bm + lr) * K + lc;
    const float* Bptr = B + (size_t)(bn + lr) * K + lc;
    const float4 zero4 = make_float4(0.f, 0.f, 0.f, 0.f);

    // preload chunk 0
    float4 a4 = aval ? *(const float4*)(Aptr) : zero4;
    float4 b4 = bval ? *(const float4*)(Bptr) : zero4;
    As[0][lc + 0][lr] = a4.x; As[0][lc + 1][lr] = a4.y;
    As[0][lc + 2][lr] = a4.z; As[0][lc + 3][lr] = a4.w;
    Bs[0][lc + 0][lr] = b4.x; Bs[0][lc + 1][lr] = b4.y;
    Bs[0][lc + 2][lr] = b4.z; Bs[0][lc + 3][lr] = b4.w;
    __syncthreads();

    int buf = 0;
    #pragma unroll 1
    for (int k0 = 0; k0 < K; k0 += 8) {
        const bool more = (k0 + 8) < K;
        if (more) {
            a4 = aval ? *(const float4*)(Aptr + k0 + 8) : zero4;
            b4 = bval ? *(const float4*)(Bptr + k0 + 8) : zero4;
        }
        #pragma unroll
        for (int kk = 0; kk < 8; kk++) {
            float ra[8], rb[8];
            *(float4*)(ra)     = *(const float4*)(&As[buf][kk][ty * 8]);
            *(float4*)(ra + 4) = *(const float4*)(&As[buf][kk][ty * 8 + 4]);
            *(float4*)(rb)     = *(const float4*)(&Bs[buf][kk][tx * 8]);
            *(float4*)(rb + 4) = *(const float4*)(&Bs[buf][kk][tx * 8 + 4]);
            #pragma unroll
            for (int i = 0; i < 8; i++)
                #pragma unroll
                for (int j = 0; j < 8; j++)
                    acc[i][j] = fmaf(ra[i], rb[j], acc[i][j]);
        }
        if (more) {
            const int nb = buf ^ 1;
            As[nb][lc + 0][lr] = a4.x; As[nb][lc + 1][lr] = a4.y;
            As[nb][lc + 2][lr] = a4.z; As[nb][lc + 3][lr] = a4.w;
            Bs[nb][lc + 0][lr] = b4.x; Bs[nb][lc + 1][lr] = b4.y;
            Bs[nb][lc + 2][lr] = b4.z; Bs[nb][lc + 3][lr] = b4.w;
            __syncthreads();
            buf = nb;
        }
    }

    // epilogue (vectorized; N % 4 == 0 at every call site)
    const int col0 = bn + tx * 8;
    #pragma unroll
    for (int i = 0; i < 8; i++) {
        const int row = bm + ty * 8 + i;
        if (row >= M) continue;
        if (col0 + 8 <= N) {
            float4 v0 = make_float4(acc[i][0], acc[i][1], acc[i][2], acc[i][3]);
            float4 v1 = make_float4(acc[i][4], acc[i][5], acc[i][6], acc[i][7]);
            if (bias1) {
                float4 t0 = *(const float4*)(bias1 + col0);
                float4 t1 = *(const float4*)(bias1 + col0 + 4);
                v0.x += t0.x; v0.y += t0.y; v0.z += t0.z; v0.w += t0.w;
                v1.x += t1.x; v1.y += t1.y; v1.z += t1.z; v1.w += t1.w;
            }
            if (bias2) {
                float4 t0 = *(const float4*)(bias2 + col0);
                float4 t1 = *(const float4*)(bias2 + col0 + 4);
                v0.x += t0.x; v0.y += t0.y; v0.z += t0.z; v0.w += t0.w;
                v1.x += t1.x; v1.y += t1.y; v1.z += t1.z; v1.w += t1.w;
            }
            if (res) {
                const float* rp = res + (size_t)row * N + col0;
                float4 t0 = *(const float4*)(rp);
                float4 t1 = *(const float4*)(rp + 4);
                v0.x += t0.x; v0.y += t0.y; v0.z += t0.z; v0.w += t0.w;
                v1.x += t1.x; v1.y += t1.y; v1.z += t1.z; v1.w += t1.w;
            }
            float* cp = C + (size_t)row * N + col0;
            *(float4*)(cp)     = v0;
            *(float4*)(cp + 4) = v1;
        } else {
            #pragma unroll
            for (int j = 0; j < 8; j++) {
                const int col = col0 + j;
                if (col >= N) continue;
                float v = acc[i][j];
                if (bias1) v += bias1[col];
                if (bias2) v += bias2[col];
                if (res)   v += res[(size_t)row * N + col];
                C[(size_t)row * N + col] = v;
            }
        }
    }
}

// ---------------- persistent LSTM: 4 groups x 32 blocks x 512 threads, 2 pipelines/block ----
#define LWP 516   // w smem pitch
#define LHP 516   // h smem pitch
__global__ __launch_bounds__(512) void lstm_persistent_kernel(
    const float* __restrict__ xg, const float* __restrict__ w_hh,
    float* __restrict__ hbuf0, float* __restrict__ hbuf1,
    float* __restrict__ lstm_out)
{
    extern __shared__ float smem[];
    float* w_sm  = smem;                     // 64 * LWP
    float* h_smA = smem + 64 * LWP;          // 4 * LHP
    float* h_smB = h_smA + 4 * LHP;          // 4 * LHP

    const int tid   = threadIdx.x;
    const int group = blockIdx.x >> 5;       // 0..3
    const int gslot = blockIdx.x & 31;       // 0..31
    const int col_base = gslot * 16;

    // Load 64 w_hh rows once: smem row r = colL*4 + q  <-  w_hh[q*512 + col_base + colL]
    for (int idx = tid; idx < 64 * 128; idx += 512) {
        int r = idx >> 7; int k4 = (idx & 127) << 2;
        int colL = r >> 2, q = r & 3;
        float4 v = *(const float4*)(w_hh + (size_t)(q * HH + col_base + colL) * HH + k4);
        float* d = w_sm + r * LWP + k4;
        d[0] = v.x; d[1] = v.y; d[2] = v.z; d[3] = v.w;
    }

    const int half = tid >> 8;               // 0 or 1
    const int t8   = tid & 255;
    const int colL = t8 >> 4;                // 0..15
    const int gate = (t8 >> 2) & 3;          // 0..3 (i,f,g,o)
    const int b4   = t8 & 3;                 // 0..3
    const int gcol  = col_base + colL;
    const int batch = group * 8 + half * 4 + b4;
    float* h_sm = half ? h_smB : h_smA;
    const float* wrow = w_sm + (colL * 4 + gate) * LWP;
    const float* hrow = h_sm + b4 * LHP;
    const size_t xgbase = (size_t)(batch * TT) * (4 * HH) + gate * HH + gcol;
    const int bar_id = 1 + half;
    const int b_base = group * 8 + half * 4;
    unsigned* my_flag = &g_flags[(blockIdx.x * 2 + half) * 32];
    float c_reg = 0.f;

    __syncthreads();   // w_sm ready, h_sm safe

    for (int t = 0; t < TT; t++) {
        const float* hprev = (t & 1) ? hbuf1 : hbuf0;
        float*       hnext = (t & 1) ? hbuf0 : hbuf1;

        if (t > 0) {
            // wait for this half's group peers to publish step t-1 h
            if (t8 < 32) {
                const unsigned* fp = &g_flags[((group * 32 + t8) * 2 + half) * 32];
                unsigned v;
                do {
                    asm volatile("ld.acquire.gpu.global.u32 %0, [%1];"
                                 : "=r"(v) : "l"(fp) : "memory");
                } while (v < (unsigned)t);
            }
            asm volatile("bar.sync %0, %1;" :: "r"(bar_id), "r"(256) : "memory");
        }

        // stage this half's h slice [4, 512] -> smem (8 KB); 2 float4 per thread
        #pragma unroll
        for (int i = 0; i < 2; i++) {
            int idx = t8 + i * 256;              // 0..511
            int row = idx >> 7; int k4 = (idx & 127) << 2;
            cp_async16(h_sm + row * LHP + k4, hprev + (b_base + row) * HH + k4);
        }
        cp_async_commit();

        float xgv = __ldg(xg + xgbase + (size_t)t * (4 * HH));

        CP_WAIT0();
        asm volatile("bar.sync %0, %1;" :: "r"(bar_id), "r"(256) : "memory");

        // gate pre-activation: dot(wrow, hrow) over 512, 4 accumulator chains
        float a0 = 0.f, a1 = 0.f, a2 = 0.f, a3 = 0.f;
        #pragma unroll
        for (int k = 0; k < HH; k += 16) {
            float4 w0 = *(const float4*)(wrow + k);
            float4 w1 = *(const float4*)(wrow + k + 4);
            float4 w2 = *(const float4*)(wrow + k + 8);
            float4 w3 = *(const float4*)(wrow + k + 12);
            float4 h0 = *(const float4*)(hrow + k);
            float4 h1 = *(const float4*)(hrow + k + 4);
            float4 h2 = *(const float4*)(hrow + k + 8);
            float4 h3 = *(const float4*)(hrow + k + 12);
            a0 = fmaf(w0.x, h0.x, a0); a1 = fmaf(w1.x, h1.x, a1);
            a2 = fmaf(w2.x, h2.x, a2); a3 = fmaf(w3.x, h3.x, a3);
            a0 = fmaf(w0.y, h0.y, a0); a1 = fmaf(w1.y, h1.y, a1);
            a2 = fmaf(w2.y, h2.y, a2); a3 = fmaf(w3.y, h3.y, a3);
            a0 = fmaf(w0.z, h0.z, a0); a1 = fmaf(w1.z, h1.z, a1);
            a2 = fmaf(w2.z, h2.z, a2); a3 = fmaf(w3.z, h3.z, a3);
            a0 = fmaf(w0.w, h0.w, a0); a1 = fmaf(w1.w, h1.w, a1);
            a2 = fmaf(w2.w, h2.w, a2); a3 = fmaf(w3.w, h3.w, a3);
        }
        float gatev = (a0 + a1) + (a2 + a3) + xgv;

        // gather f,g,o from lanes +4,+8,+12 (same col, same batch)
        float fv = __shfl_down_sync(0xffffffffu, gatev, 4);
        float gv = __shfl_down_sync(0xffffffffu, gatev, 8);
        float ov = __shfl_down_sync(0xffffffffu, gatev, 12);

        if (gate == 0) {
            float ig = 1.f / (1.f + __expf(-gatev));
            float fg = 1.f / (1.f + __expf(-fv));
            float og = 1.f / (1.f + __expf(-ov));
            float gg = tanhf(gv);
            c_reg = fg * c_reg + ig * gg;
            float hn = og * tanhf(c_reg);
            __stcg(hnext + batch * HH + gcol, hn);
            __stcg(lstm_out + (size_t)(batch * TT + t) * HH + gcol, hn);
        }
        asm volatile("bar.sync %0, %1;" :: "r"(bar_id), "r"(256) : "memory");

        // publish (single fence + release store per half)
        if (t8 == 0) {
            asm volatile("fence.acq_rel.gpu;" ::: "memory");
            asm volatile("st.release.gpu.global.u32 [%0], %1;"
                         :: "l"(my_flag), "r"((unsigned)(t + 1)) : "memory");
        }
    }
}

// ---------------- fused attention: per (t-chunk, head, batch) ----------------
#define KTP 257   // transposed K/V pitch (257 mod 32 == 1 -> conflict-free lane stride)
#define QSP 68
#define PSP 260
__global__ __launch_bounds__(256) void attn_kernel(
    const float* __restrict__ q, const float* __restrict__ kmat,
    const float* __restrict__ vmat, float* __restrict__ ctx)
{
    extern __shared__ float smem[];
    float* Kt   = smem;                    // [64][KTP]
    float* Vt   = Kt + 64 * KTP;           // [64][KTP]
    float* qs   = Vt + 64 * KTP;           // [32][QSP]
    float* ps   = qs + 32 * QSP;           // [32][PSP]
    float* sums = ps + 32 * PSP;           // [32]

    const int t0 = blockIdx.x * 32;
    const int h  = blockIdx.y;
    const int b  = blockIdx.z;
    const int tid = threadIdx.x;

    // load K,V transposed: Kt[d][s] = K[b*256+s][h*64+d]
    for (int idx = tid; idx < 256 * 16; idx += 256) {
        int s = idx >> 4; int d4 = (idx & 15) << 2;
        size_t off = (size_t)(b * SS + s) * HH + h * HDD + d4;
        float4 kv = *(const float4*)(kmat + off);
        Kt[(d4 + 0) * KTP + s] = kv.x; Kt[(d4 + 1) * KTP + s] = kv.y;
        Kt[(d4 + 2) * KTP + s] = kv.z; Kt[(d4 + 3) * KTP + s] = kv.w;
        float4 vv = *(const float4*)(vmat + off);
        Vt[(d4 + 0) * KTP + s] = vv.x; Vt[(d4 + 1) * KTP + s] = vv.y;
        Vt[(d4 + 2) * KTP + s] = vv.z; Vt[(d4 + 3) * KTP + s] = vv.w;
    }
    // load q chunk
    for (int idx = tid; idx < 32 * 16; idx += 256) {
        int r = idx >> 4; int d4 = (idx & 15) << 2;
        int trow = t0 + r;
        float4 qv = make_float4(0.f, 0.f, 0.f, 0.f);
        if (trow < TT)
            qv = *(const float4*)(q + (size_t)(b * TT + trow) * HH + h * HDD + d4);
        float* d = qs + r * QSP + d4;
        d[0] = qv.x; d[1] = qv.y; d[2] = qv.z; d[3] = qv.w;
    }
    __syncthreads();

    const int r  = tid >> 3;  // query row in chunk
    const int lc = tid & 7;   // lane-col

    float qreg[64];
    #pragma unroll
    for (int d = 0; d < 64; d++) qreg[d] = qs[r * QSP + d];

    float sc[32];
    for (int si = 0; si < 32; si++) {
        int s = si * 8 + lc;
        float acc = 0.f;
        #pragma unroll
        for (int d = 0; d < 64; d++) acc += qreg[d] * Kt[d * KTP + s];
        sc[si] = acc * 0.125f;   // 1/sqrt(64)
    }
    float m = -1e30f;
    #pragma unroll
    for (int si = 0; si < 32; si++) m = fmaxf(m, sc[si]);
    m = fmaxf(m, __shfl_xor_sync(0xffffffff, m, 1));
    m = fmaxf(m, __shfl_xor_sync(0xffffffff, m, 2));
    m = fmaxf(m, __shfl_xor_sync(0xffffffff, m, 4));
    float ssum = 0.f;
    #pragma unroll
    for (int si = 0; si < 32; si++) {
        float e = __expf(sc[si] - m);
        ssum += e;
        ps[r * PSP + si * 8 + lc] = e;
    }
    ssum += __shfl_xor_sync(0xffffffff, ssum, 1);
    ssum += __shfl_xor_sync(0xffffffff, ssum, 2);
    ssum += __shfl_xor_sync(0xffffffff, ssum, 4);
    if (lc == 0) sums[r] = ssum;
    __syncthreads();

    // ctx: thread covers d = lc + 8j
    float accv[8];
    #pragma unroll
    for (int j = 0; j < 8; j++) accv[j] = 0.f;
    const float* prow = ps + r * PSP;
    #pragma unroll 4
    for (int s = 0; s < 256; s++) {
        float pv = prow[s];
        #pragma unroll
        for (int j = 0; j < 8; j++)
            accv[j] += pv * Vt[(lc + 8 * j) * KTP + s];
    }
    float inv = 1.0f / sums[r];
    int trow = t0 + r;
    if (trow < TT) {
        float* dst = ctx + (size_t)(b * TT + trow) * HH + h * HDD;
        #pragma unroll
        for (int j = 0; j < 8; j++) dst[lc + 8 * j] = accv[j] * inv;
    }
}

// ---------------- launch ----------------
extern "C" void kernel_launch(void* const* d_in, const int* in_sizes, int n_in,
                              void* d_out, int out_size) {
    const int*   targets  = (const int*)  d_in[0];
    const float* enc      = (const float*)d_in[1];
    const float* embedding= (const float*)d_in[2];
    const float* w_ih     = (const float*)d_in[3];
    const float* w_hh     = (const float*)d_in[4];
    const float* b_ih     = (const float*)d_in[5];
    const float* b_hh     = (const float*)d_in[6];
    const float* in_proj_w= (const float*)d_in[7];
    const float* in_proj_b= (const float*)d_in[8];
    const float* out_proj_w=(const float*)d_in[9];
    const float* out_proj_b=(const float*)d_in[10];
    const float* fc_w     = (const float*)d_in[11];
    const float* fc_b     = (const float*)d_in[12];
    float* out = (float*)d_out;

    float *p_emb, *p_xg, *p_h, *p_lstm, *p_q, *p_k, *p_v, *p_ctx, *p_comb;
    cudaGetSymbolAddress((void**)&p_emb,  g_emb);
    cudaGetSymbolAddress((void**)&p_xg,   g_xg);
    cudaGetSymbolAddress((void**)&p_h,    g_h);
    cudaGetSymbolAddress((void**)&p_lstm, g_lstm);
    cudaGetSymbolAddress((void**)&p_q,    g_q);
    cudaGetSymbolAddress((void**)&p_k,    g_k);
    cudaGetSymbolAddress((void**)&p_v,    g_v);
    cudaGetSymbolAddress((void**)&p_ctx,  g_ctx);
    cudaGetSymbolAddress((void**)&p_comb, g_comb);
    float* h_buf0 = p_h;
    float* h_buf1 = p_h + BB * HH;

    const int lstm_smem = (64 * LWP + 8 * LHP) * (int)sizeof(float);   // ~145 KB
    const int attn_smem = (64 * KTP * 2 + 32 * QSP + 32 * PSP + 32) * (int)sizeof(float);
    cudaFuncSetAttribute(lstm_persistent_kernel, cudaFuncAttributeMaxDynamicSharedMemorySize, lstm_smem);
    cudaFuncSetAttribute(attn_kernel,            cudaFuncAttributeMaxDynamicSharedMemorySize, attn_smem);

    // 1. zero h0 + flags
    zero_kernel<<<(BB * HH + 255) / 256, 256>>>(h_buf0, BB * HH);

    // 2. gather embeddings
    gather_kernel<<<BT, 128>>>(targets, embedding, p_emb);

    // 3. xg = emb @ w_ih^T + b_ih + b_hh   [4064, 2048]
    {
        dim3 grid((4 * HH + 127) / 128, (BT + 127) / 128);
        sgemm_kernel<<<grid, 256>>>(p_emb, w_ih, b_ih, b_hh, nullptr, p_xg, BT, 4 * HH, HH);
    }

    // 4. LSTM recurrence — one persistent kernel, dual pipelines per block
    lstm_persistent_kernel<<<NBLK, 512, lstm_smem>>>(p_xg, w_hh, h_buf0, h_buf1, p_lstm);

    // 5. q/k/v projections
    {
        dim3 gq((HH + 127) / 128, (BT + 127) / 128);
        sgemm_kernel<<<gq, 256>>>(p_lstm, in_proj_w, in_proj_b, nullptr, nullptr, p_q, BT, HH, HH);
        dim3 gk((HH + 127) / 128, (BS + 127) / 128);
        sgemm_kernel<<<gk, 256>>>(enc, in_proj_w + (size_t)HH * HH, in_proj_b + HH,
                                  nullptr, nullptr, p_k, BS, HH, HH);
        sgemm_kernel<<<gk, 256>>>(enc, in_proj_w + (size_t)2 * HH * HH, in_proj_b + 2 * HH,
                                  nullptr, nullptr, p_v, BS, HH, HH);
    }

    // 6. fused attention -> ctx
    {
        dim3 grid(4, NHH, BB);
        attn_kernel<<<grid, 256, attn_smem>>>(p_q, p_k, p_v, p_ctx);
    }

    // 7. combined = ctx @ out_proj^T + out_proj_b + lstm_out
    {
        dim3 grid((HH + 127) / 128, (BT + 127) / 128);
        sgemm_kernel<<<grid, 256>>>(p_ctx, out_proj_w, out_proj_b, nullptr, p_lstm, p_comb, BT, HH, HH);
    }

    // 8. out = combined @ fc_w^T + fc_b   [4064, 8000]
    {
        dim3 grid((VV + 127) / 128, (BT + 127) / 128);
        sgemm_kernel<<<grid, 256>>>(p_comb, fc_w, fc_b, nullptr, nullptr, out, BT, VV, HH);
    }
}

// round 10
// speedup vs baseline: 1.6405x; 1.4603x over previous
#include <cuda_runtime.h>
#include <cuda_bf16.h>
#include <math.h>
#include <stdint.h>

// Problem constants
#define BB   32
#define TT   127
#define SS   256
#define HH   512
#define VV   8000
#define NHH  8
#define HDD  64
#define BT   (BB*TT)      // 4064
#define BS   (BB*SS)      // 8192
#define NBLK 128          // persistent LSTM grid (4 groups x 32 blocks)
#define MPAD 4096         // BT padded to tile multiple
#define VPAD 8064         // VV padded to tile multiple (63*128)

// ---------------- scratch (device globals; no allocations allowed) ----------------
__device__ float g_emb [BT * HH];
__device__ float g_xg  [BT * 4 * HH];
__device__ float g_h   [2][BB * HH];
__device__ float g_lstm[BT * HH];
__device__ float g_q   [BT * HH];
__device__ float g_k   [BS * HH];
__device__ float g_v   [BS * HH];
__device__ float g_ctx [BT * HH];
__device__ float g_comb[BT * HH];
__device__ unsigned g_flags[NBLK * 2 * 32];

// bf16 hi/lo split buffers (padded to tile multiples; pad stays zero)
__device__ __nv_bfloat16 g_embh [MPAD * HH], g_embl [MPAD * HH];
__device__ __nv_bfloat16 g_lstmh[MPAD * HH], g_lstml[MPAD * HH];
__device__ __nv_bfloat16 g_ctxh [MPAD * HH], g_ctxl [MPAD * HH];
__device__ __nv_bfloat16 g_combh[MPAD * HH], g_combl[MPAD * HH];
__device__ __nv_bfloat16 g_ench [BS * HH],   g_encl [BS * HH];
__device__ __nv_bfloat16 g_wihh [4*HH*HH],   g_wihl [4*HH*HH];
__device__ __nv_bfloat16 g_inph [3*HH*HH],   g_inpl [3*HH*HH];
__device__ __nv_bfloat16 g_outph[HH*HH],     g_outpl[HH*HH];
__device__ __nv_bfloat16 g_fcwh [VPAD * HH], g_fcwl [VPAD * HH];

// ---------------- cp.async helpers ----------------
__device__ __forceinline__ void cp_async16(uint32_t dst_smem, const void* src_gmem) {
    asm volatile("cp.async.cg.shared.global [%0], [%1], 16;\n" :: "r"(dst_smem), "l"(src_gmem));
}
__device__ __forceinline__ void cp_async16f(float* dst_smem, const float* src_gmem) {
    unsigned s = (unsigned)__cvta_generic_to_shared(dst_smem);
    asm volatile("cp.async.cg.shared.global [%0], [%1], 16;\n" :: "r"(s), "l"(src_gmem));
}
__device__ __forceinline__ void cp_async_commit() { asm volatile("cp.async.commit_group;\n"); }
#define CP_WAITN(n) asm volatile("cp.async.wait_group %0;\n" :: "n"(n))

__device__ __forceinline__ uint32_t s2u(const void* p) {
    uint32_t a;
    asm("{ .reg .u64 t; cvta.to.shared.u64 t, %1; cvt.u32.u64 %0, t; }" : "=r"(a) : "l"(p));
    return a;
}

// ---------------- mma helpers ----------------
#define LDSM_X4(r0, r1, r2, r3, addr)                                              \
    asm volatile("ldmatrix.sync.aligned.m8n8.x4.shared.b16 {%0,%1,%2,%3}, [%4];"   \
        : "=r"(r0), "=r"(r1), "=r"(r2), "=r"(r3) : "r"(addr))
#define LDSM_X2(r0, r1, addr)                                                      \
    asm volatile("ldmatrix.sync.aligned.m8n8.x2.shared.b16 {%0,%1}, [%2];"         \
        : "=r"(r0), "=r"(r1) : "r"(addr))
#define MMA16816(d, a, b)                                                          \
    asm volatile("mma.sync.aligned.m16n8k16.row.col.f32.bf16.bf16.f32 "            \
        "{%0,%1,%2,%3},{%4,%5,%6,%7},{%8,%9},{%0,%1,%2,%3};"                       \
        : "+f"((d)[0]), "+f"((d)[1]), "+f"((d)[2]), "+f"((d)[3])                   \
        : "r"((a)[0]), "r"((a)[1]), "r"((a)[2]), "r"((a)[3]),                      \
          "r"((b)[0]), "r"((b)[1]))

// ---------------- init: zero h0 and flags ----------------
__global__ void zero_kernel(float* h0, int n) {
    int i = blockIdx.x * blockDim.x + threadIdx.x;
    if (i < n) h0[i] = 0.f;
    if (i < NBLK * 2 * 32) g_flags[i] = 0u;
}

// ---------------- embedding gather ----------------
__global__ void gather_kernel(const int* __restrict__ targets,
                              const float* __restrict__ table,
                              float* __restrict__ out) {
    int bt = blockIdx.x;
    int b = bt / TT, t = bt - b * TT;
    int tok = targets[b * 128 + t];
    const float4* src = (const float4*)(table + (size_t)tok * HH);
    float4* dst = (float4*)(out + (size_t)bt * HH);
    dst[threadIdx.x] = src[threadIdx.x];
}

// ---------------- fp32 -> bf16 hi/lo split ----------------
__global__ void split_kernel(const float* __restrict__ x,
                             __nv_bfloat16* __restrict__ hi,
                             __nv_bfloat16* __restrict__ lo, int n) {
    int i4 = (blockIdx.x * blockDim.x + threadIdx.x) * 4;
    if (i4 < n) {
        float4 v = *(const float4*)(x + i4);
        __nv_bfloat16 hx = __float2bfloat16_rn(v.x);
        __nv_bfloat16 hy = __float2bfloat16_rn(v.y);
        __nv_bfloat16 hz = __float2bfloat16_rn(v.z);
        __nv_bfloat16 hw = __float2bfloat16_rn(v.w);
        __nv_bfloat16 lx = __float2bfloat16_rn(v.x - __bfloat162float(hx));
        __nv_bfloat16 ly = __float2bfloat16_rn(v.y - __bfloat162float(hy));
        __nv_bfloat16 lz = __float2bfloat16_rn(v.z - __bfloat162float(hz));
        __nv_bfloat16 lw = __float2bfloat16_rn(v.w - __bfloat162float(hw));
        *(__nv_bfloat162*)(hi + i4)     = __halves2bfloat162(hx, hy);
        *(__nv_bfloat162*)(hi + i4 + 2) = __halves2bfloat162(hz, hw);
        *(__nv_bfloat162*)(lo + i4)     = __halves2bfloat162(lx, ly);
        *(__nv_bfloat162*)(lo + i4 + 2) = __halves2bfloat162(lz, lw);
    }
}

// ---------------- tensor-core GEMM via mma.sync: C[M,N]=A[M,K]@B[N,K]^T (3xbf16) ----------------
// 128x128 block tile, 256 threads (2x4 warps, 64x32 warp tile), BK=32 double-buffered.
// smem per matrix chunk: [128 rows][40 halves] (80B pitch, conflict-free ldmatrix phases).
#define AP   40
#define SEG  (128 * AP * 2)    // 10240 bytes per matrix chunk buffer
__global__ __launch_bounds__(256) void mma_gemm(
    const __nv_bfloat16* __restrict__ Ah, const __nv_bfloat16* __restrict__ Al,
    const __nv_bfloat16* __restrict__ Bh, const __nv_bfloat16* __restrict__ Bl,
    const float* __restrict__ bias1, const float* __restrict__ bias2,
    const float* __restrict__ res, float* __restrict__ C,
    int M, int N, int K)
{
    extern __shared__ char smem[];
    const uint32_t sb = s2u(smem);
    const int tid  = threadIdx.x;
    const int wid  = tid >> 5;
    const int lane = tid & 31;
    const int wm = wid >> 2;          // 0..1
    const int wn = wid & 3;           // 0..3
    const int m0 = blockIdx.y * 128;
    const int n0 = blockIdx.x * 128;

    float acc[4][4][4];
    #pragma unroll
    for (int i = 0; i < 4; i++)
        #pragma unroll
        for (int j = 0; j < 4; j++)
            #pragma unroll
            for (int r = 0; r < 4; r++) acc[i][j][r] = 0.f;

    const __nv_bfloat16* srcAh = Ah + (size_t)m0 * K;
    const __nv_bfloat16* srcAl = Al + (size_t)m0 * K;
    const __nv_bfloat16* srcBh = Bh + (size_t)n0 * K;
    const __nv_bfloat16* srcBl = Bl + (size_t)n0 * K;

    // issue one 32-wide K chunk (4 matrices x 128 rows x 64B) into buffer `buf`
    auto issue = [&](int k0, int buf) {
        #pragma unroll
        for (int t = 0; t < 8; t++) {
            int idx = tid + t * 256;             // 0..2047
            int mat = idx >> 9;                  // 0..3
            int r   = (idx >> 2) & 127;
            int j   = idx & 3;
            uint32_t dst = sb + (uint32_t)(mat * 2 + buf) * SEG
                         + (uint32_t)(r * AP + j * 8) * 2;
            const __nv_bfloat16* s =
                (mat == 0 ? srcAh : mat == 1 ? srcAl : mat == 2 ? srcBh : srcBl)
                + (size_t)r * K + k0 + j * 8;
            cp_async16(dst, s);
        }
        cp_async_commit();
    };

    // ldmatrix per-lane offsets
    const uint32_t a_off = (uint32_t)(((wm * 64 + (lane & 15)) * AP + (lane >> 4) * 8) * 2);
    const uint32_t b_off = (uint32_t)(((wn * 32 + (lane & 7)) * AP + ((lane >> 3) & 1) * 8) * 2);

    const int NC = K / 32;
    issue(0, 0);
    #pragma unroll 1
    for (int c = 0; c < NC; c++) {
        const int buf = c & 1;
        if (c + 1 < NC) {
            issue((c + 1) * 32, buf ^ 1);
            CP_WAITN(1);
        } else {
            CP_WAITN(0);
        }
        __syncthreads();

        #pragma unroll
        for (int ks = 0; ks < 2; ks++) {
            const uint32_t kb = (uint32_t)(ks * 32);   // 16 halves = 32 bytes
            uint32_t bh[4][2], bl[4][2];
            #pragma unroll
            for (int nt = 0; nt < 4; nt++) {
                uint32_t ba = sb + (uint32_t)(4 + buf) * SEG + b_off
                            + (uint32_t)(nt * 8 * AP * 2) + kb;
                LDSM_X2(bh[nt][0], bh[nt][1], ba);
                LDSM_X2(bl[nt][0], bl[nt][1], ba + 2u * SEG);
            }
            #pragma unroll
            for (int mt = 0; mt < 4; mt++) {
                uint32_t ah[4], al[4];
                uint32_t aa = sb + (uint32_t)buf * SEG + a_off
                            + (uint32_t)(mt * 16 * AP * 2) + kb;
                LDSM_X4(ah[0], ah[1], ah[2], ah[3], aa);
                LDSM_X4(al[0], al[1], al[2], al[3], aa + 2u * SEG);
                #pragma unroll
                for (int nt = 0; nt < 4; nt++) {
                    MMA16816(acc[mt][nt], ah, bh[nt]);
                    MMA16816(acc[mt][nt], ah, bl[nt]);
                    MMA16816(acc[mt][nt], al, bh[nt]);
                }
            }
        }
        __syncthreads();
    }

    // epilogue: m16n8 fragment mapping -> float2 stores with fused bias/residual
    const int tm = lane >> 2;
    const int tc = (lane & 3) * 2;
    #pragma unroll
    for (int mt = 0; mt < 4; mt++) {
        #pragma unroll
        for (int nt = 0; nt < 4; nt++) {
            int col = n0 + wn * 32 + nt * 8 + tc;
            if (col >= N) continue;              // col,N both even -> col+1 < N too
            float2 v0 = make_float2(acc[mt][nt][0], acc[mt][nt][1]);
            float2 v1 = make_float2(acc[mt][nt][2], acc[mt][nt][3]);
            if (bias1) {
                float2 b = *(const float2*)(bias1 + col);
                v0.x += b.x; v0.y += b.y; v1.x += b.x; v1.y += b.y;
            }
            if (bias2) {
                float2 b = *(const float2*)(bias2 + col);
                v0.x += b.x; v0.y += b.y; v1.x += b.x; v1.y += b.y;
            }
            int row0 = m0 + wm * 64 + mt * 16 + tm;
            if (row0 < M) {
                float2 o = v0;
                if (res) {
                    float2 rr = *(const float2*)(res + (size_t)row0 * N + col);
                    o.x += rr.x; o.y += rr.y;
                }
                *(float2*)(C + (size_t)row0 * N + col) = o;
            }
            int row1 = row0 + 8;
            if (row1 < M) {
                float2 o = v1;
                if (res) {
                    float2 rr = *(const float2*)(res + (size_t)row1 * N + col);
                    o.x += rr.x; o.y += rr.y;
                }
                *(float2*)(C + (size_t)row1 * N + col) = o;
            }
        }
    }
}

// ---------------- persistent LSTM: 4 groups x 32 blocks x 512 threads, 2 pipelines/block ----
#define LWP 516
#define LHP 516
__global__ __launch_bounds__(512) void lstm_persistent_kernel(
    const float* __restrict__ xg, const float* __restrict__ w_hh,
    float* __restrict__ hbuf0, float* __restrict__ hbuf1,
    float* __restrict__ lstm_out)
{
    extern __shared__ float smemf[];
    float* w_sm  = smemf;
    float* h_smA = smemf + 64 * LWP;
    float* h_smB = h_smA + 4 * LHP;

    const int tid   = threadIdx.x;
    const int group = blockIdx.x >> 5;
    const int gslot = blockIdx.x & 31;
    const int col_base = gslot * 16;

    for (int idx = tid; idx < 64 * 128; idx += 512) {
        int r = idx >> 7; int k4 = (idx & 127) << 2;
        int colL = r >> 2, q = r & 3;
        float4 v = *(const float4*)(w_hh + (size_t)(q * HH + col_base + colL) * HH + k4);
        float* d = w_sm + r * LWP + k4;
        d[0] = v.x; d[1] = v.y; d[2] = v.z; d[3] = v.w;
    }

    const int half = tid >> 8;
    const int t8   = tid & 255;
    const int colL = t8 >> 4;
    const int gate = (t8 >> 2) & 3;
    const int b4   = t8 & 3;
    const int gcol  = col_base + colL;
    const int batch = group * 8 + half * 4 + b4;
    float* h_sm = half ? h_smB : h_smA;
    const float* wrow = w_sm + (colL * 4 + gate) * LWP;
    const float* hrow = h_sm + b4 * LHP;
    const size_t xgbase = (size_t)(batch * TT) * (4 * HH) + gate * HH + gcol;
    const int bar_id = 1 + half;
    const int b_base = group * 8 + half * 4;
    unsigned* my_flag = &g_flags[(blockIdx.x * 2 + half) * 32];
    float c_reg = 0.f;

    __syncthreads();

    for (int t = 0; t < TT; t++) {
        const float* hprev = (t & 1) ? hbuf1 : hbuf0;
        float*       hnext = (t & 1) ? hbuf0 : hbuf1;

        if (t > 0) {
            if (t8 < 32) {
                const unsigned* fp = &g_flags[((group * 32 + t8) * 2 + half) * 32];
                unsigned v;
                do {
                    asm volatile("ld.acquire.gpu.global.u32 %0, [%1];"
                                 : "=r"(v) : "l"(fp) : "memory");
                } while (v < (unsigned)t);
            }
            asm volatile("bar.sync %0, %1;" :: "r"(bar_id), "r"(256) : "memory");
        }

        #pragma unroll
        for (int i = 0; i < 2; i++) {
            int idx = t8 + i * 256;
            int row = idx >> 7; int k4 = (idx & 127) << 2;
            cp_async16f(h_sm + row * LHP + k4, hprev + (b_base + row) * HH + k4);
        }
        cp_async_commit();

        float xgv = __ldg(xg + xgbase + (size_t)t * (4 * HH));

        CP_WAITN(0);
        asm volatile("bar.sync %0, %1;" :: "r"(bar_id), "r"(256) : "memory");

        float a0 = 0.f, a1 = 0.f, a2 = 0.f, a3 = 0.f;
        #pragma unroll
        for (int k = 0; k < HH; k += 16) {
            float4 w0 = *(const float4*)(wrow + k);
            float4 w1 = *(const float4*)(wrow + k + 4);
            float4 w2 = *(const float4*)(wrow + k + 8);
            float4 w3 = *(const float4*)(wrow + k + 12);
            float4 h0 = *(const float4*)(hrow + k);
            float4 h1 = *(const float4*)(hrow + k + 4);
            float4 h2 = *(const float4*)(hrow + k + 8);
            float4 h3 = *(const float4*)(hrow + k + 12);
            a0 = fmaf(w0.x, h0.x, a0); a1 = fmaf(w1.x, h1.x, a1);
            a2 = fmaf(w2.x, h2.x, a2); a3 = fmaf(w3.x, h3.x, a3);
            a0 = fmaf(w0.y, h0.y, a0); a1 = fmaf(w1.y, h1.y, a1);
            a2 = fmaf(w2.y, h2.y, a2); a3 = fmaf(w3.y, h3.y, a3);
            a0 = fmaf(w0.z, h0.z, a0); a1 = fmaf(w1.z, h1.z, a1);
            a2 = fmaf(w2.z, h2.z, a2); a3 = fmaf(w3.z, h3.z, a3);
            a0 = fmaf(w0.w, h0.w, a0); a1 = fmaf(w1.w, h1.w, a1);
            a2 = fmaf(w2.w, h2.w, a2); a3 = fmaf(w3.w, h3.w, a3);
        }
        float gatev = (a0 + a1) + (a2 + a3) + xgv;

        float fv = __shfl_down_sync(0xffffffffu, gatev, 4);
        float gv = __shfl_down_sync(0xffffffffu, gatev, 8);
        float ov = __shfl_down_sync(0xffffffffu, gatev, 12);

        if (gate == 0) {
            float ig = 1.f / (1.f + __expf(-gatev));
            float fg = 1.f / (1.f + __expf(-fv));
            float og = 1.f / (1.f + __expf(-ov));
            float gg = tanhf(gv);
            c_reg = fg * c_reg + ig * gg;
            float hn = og * tanhf(c_reg);
            __stcg(hnext + batch * HH + gcol, hn);
            __stcg(lstm_out + (size_t)(batch * TT + t) * HH + gcol, hn);
        }
        asm volatile("bar.sync %0, %1;" :: "r"(bar_id), "r"(256) : "memory");

        if (t8 == 0) {
            asm volatile("fence.acq_rel.gpu;" ::: "memory");
            asm volatile("st.release.gpu.global.u32 [%0], %1;"
                         :: "l"(my_flag), "r"((unsigned)(t + 1)) : "memory");
        }
    }
}

// ---------------- fused attention: per (t-chunk, head, batch) ----------------
#define KTP 257
#define QSP 68
#define PSP 260
__global__ __launch_bounds__(256) void attn_kernel(
    const float* __restrict__ q, const float* __restrict__ kmat,
    const float* __restrict__ vmat, float* __restrict__ ctx)
{
    extern __shared__ float smemf[];
    float* Kt   = smemf;
    float* Vt   = Kt + 64 * KTP;
    float* qs   = Vt + 64 * KTP;
    float* ps   = qs + 32 * QSP;
    float* sums = ps + 32 * PSP;

    const int t0 = blockIdx.x * 32;
    const int h  = blockIdx.y;
    const int b  = blockIdx.z;
    const int tid = threadIdx.x;

    for (int idx = tid; idx < 256 * 16; idx += 256) {
        int s = idx >> 4; int d4 = (idx & 15) << 2;
        size_t off = (size_t)(b * SS + s) * HH + h * HDD + d4;
        float4 kv = *(const float4*)(kmat + off);
        Kt[(d4 + 0) * KTP + s] = kv.x; Kt[(d4 + 1) * KTP + s] = kv.y;
        Kt[(d4 + 2) * KTP + s] = kv.z; Kt[(d4 + 3) * KTP + s] = kv.w;
        float4 vv = *(const float4*)(vmat + off);
        Vt[(d4 + 0) * KTP + s] = vv.x; Vt[(d4 + 1) * KTP + s] = vv.y;
        Vt[(d4 + 2) * KTP + s] = vv.z; Vt[(d4 + 3) * KTP + s] = vv.w;
    }
    for (int idx = tid; idx < 32 * 16; idx += 256) {
        int r = idx >> 4; int d4 = (idx & 15) << 2;
        int trow = t0 + r;
        float4 qv = make_float4(0.f, 0.f, 0.f, 0.f);
        if (trow < TT)
            qv = *(const float4*)(q + (size_t)(b * TT + trow) * HH + h * HDD + d4);
        float* d = qs + r * QSP + d4;
        d[0] = qv.x; d[1] = qv.y; d[2] = qv.z; d[3] = qv.w;
    }
    __syncthreads();

    const int r  = tid >> 3;
    const int lc = tid & 7;

    float qreg[64];
    #pragma unroll
    for (int d = 0; d < 64; d++) qreg[d] = qs[r * QSP + d];

    float sc[32];
    for (int si = 0; si < 32; si++) {
        int s = si * 8 + lc;
        float acc = 0.f;
        #pragma unroll
        for (int d = 0; d < 64; d++) acc += qreg[d] * Kt[d * KTP + s];
        sc[si] = acc * 0.125f;
    }
    float m = -1e30f;
    #pragma unroll
    for (int si = 0; si < 32; si++) m = fmaxf(m, sc[si]);
    m = fmaxf(m, __shfl_xor_sync(0xffffffff, m, 1));
    m = fmaxf(m, __shfl_xor_sync(0xffffffff, m, 2));
    m = fmaxf(m, __shfl_xor_sync(0xffffffff, m, 4));
    float ssum = 0.f;
    #pragma unroll
    for (int si = 0; si < 32; si++) {
        float e = __expf(sc[si] - m);
        ssum += e;
        ps[r * PSP + si * 8 + lc] = e;
    }
    ssum += __shfl_xor_sync(0xffffffff, ssum, 1);
    ssum += __shfl_xor_sync(0xffffffff, ssum, 2);
    ssum += __shfl_xor_sync(0xffffffff, ssum, 4);
    if (lc == 0) sums[r] = ssum;
    __syncthreads();

    float accv[8];
    #pragma unroll
    for (int j = 0; j < 8; j++) accv[j] = 0.f;
    const float* prow = ps + r * PSP;
    #pragma unroll 4
    for (int s = 0; s < 256; s++) {
        float pv = prow[s];
        #pragma unroll
        for (int j = 0; j < 8; j++)
            accv[j] += pv * Vt[(lc + 8 * j) * KTP + s];
    }
    float inv = 1.0f / sums[r];
    int trow = t0 + r;
    if (trow < TT) {
        float* dst = ctx + (size_t)(b * TT + trow) * HH + h * HDD;
        #pragma unroll
        for (int j = 0; j < 8; j++) dst[lc + 8 * j] = accv[j] * inv;
    }
}

// ---------------- launch ----------------
extern "C" void kernel_launch(void* const* d_in, const int* in_sizes, int n_in,
                              void* d_out, int out_size) {
    const int*   targets  = (const int*)  d_in[0];
    const float* enc      = (const float*)d_in[1];
    const float* embedding= (const float*)d_in[2];
    const float* w_ih     = (const float*)d_in[3];
    const float* w_hh     = (const float*)d_in[4];
    const float* b_ih     = (const float*)d_in[5];
    const float* b_hh     = (const float*)d_in[6];
    const float* in_proj_w= (const float*)d_in[7];
    const float* in_proj_b= (const float*)d_in[8];
    const float* out_proj_w=(const float*)d_in[9];
    const float* out_proj_b=(const float*)d_in[10];
    const float* fc_w     = (const float*)d_in[11];
    const float* fc_b     = (const float*)d_in[12];
    float* out = (float*)d_out;

    float *p_emb, *p_xg, *p_h, *p_lstm, *p_q, *p_k, *p_v, *p_ctx, *p_comb;
    cudaGetSymbolAddress((void**)&p_emb,  g_emb);
    cudaGetSymbolAddress((void**)&p_xg,   g_xg);
    cudaGetSymbolAddress((void**)&p_h,    g_h);
    cudaGetSymbolAddress((void**)&p_lstm, g_lstm);
    cudaGetSymbolAddress((void**)&p_q,    g_q);
    cudaGetSymbolAddress((void**)&p_k,    g_k);
    cudaGetSymbolAddress((void**)&p_v,    g_v);
    cudaGetSymbolAddress((void**)&p_ctx,  g_ctx);
    cudaGetSymbolAddress((void**)&p_comb, g_comb);
    __nv_bfloat16 *p_embh, *p_embl, *p_lstmh, *p_lstml, *p_ctxh, *p_ctxl,
                  *p_combh, *p_combl, *p_ench, *p_encl, *p_wihh, *p_wihl,
                  *p_inph, *p_inpl, *p_outph, *p_outpl, *p_fcwh, *p_fcwl;
    cudaGetSymbolAddress((void**)&p_embh,  g_embh);
    cudaGetSymbolAddress((void**)&p_embl,  g_embl);
    cudaGetSymbolAddress((void**)&p_lstmh, g_lstmh);
    cudaGetSymbolAddress((void**)&p_lstml, g_lstml);
    cudaGetSymbolAddress((void**)&p_ctxh,  g_ctxh);
    cudaGetSymbolAddress((void**)&p_ctxl,  g_ctxl);
    cudaGetSymbolAddress((void**)&p_combh, g_combh);
    cudaGetSymbolAddress((void**)&p_combl, g_combl);
    cudaGetSymbolAddress((void**)&p_ench,  g_ench);
    cudaGetSymbolAddress((void**)&p_encl,  g_encl);
    cudaGetSymbolAddress((void**)&p_wihh,  g_wihh);
    cudaGetSymbolAddress((void**)&p_wihl,  g_wihl);
    cudaGetSymbolAddress((void**)&p_inph,  g_inph);
    cudaGetSymbolAddress((void**)&p_inpl,  g_inpl);
    cudaGetSymbolAddress((void**)&p_outph, g_outph);
    cudaGetSymbolAddress((void**)&p_outpl, g_outpl);
    cudaGetSymbolAddress((void**)&p_fcwh,  g_fcwh);
    cudaGetSymbolAddress((void**)&p_fcwl,  g_fcwl);

    float* h_buf0 = p_h;
    float* h_buf1 = p_h + BB * HH;

    const int lstm_smem = (64 * LWP + 8 * LHP) * (int)sizeof(float);
    const int attn_smem = (64 * KTP * 2 + 32 * QSP + 32 * PSP + 32) * (int)sizeof(float);
    const int mma_smem  = 8 * SEG;     // 81920
    cudaFuncSetAttribute(lstm_persistent_kernel, cudaFuncAttributeMaxDynamicSharedMemorySize, lstm_smem);
    cudaFuncSetAttribute(attn_kernel,            cudaFuncAttributeMaxDynamicSharedMemorySize, attn_smem);
    cudaFuncSetAttribute(mma_gemm,               cudaFuncAttributeMaxDynamicSharedMemorySize, mma_smem);

    #define SPLIT(src, hi, lo, n) split_kernel<<<((n)/4 + 255) / 256, 256>>>(src, hi, lo, n)

    // 1. zero h0 + flags
    zero_kernel<<<(BB * HH + 255) / 256, 256>>>(h_buf0, BB * HH);

    // 2. weight/input splits
    SPLIT(w_ih,       p_wihh,  p_wihl,  4 * HH * HH);
    SPLIT(in_proj_w,  p_inph,  p_inpl,  3 * HH * HH);
    SPLIT(out_proj_w, p_outph, p_outpl, HH * HH);
    SPLIT(fc_w,       p_fcwh,  p_fcwl,  VV * HH);
    SPLIT(enc,        p_ench,  p_encl,  BS * HH);

    // 3. gather embeddings + split
    gather_kernel<<<BT, 128>>>(targets, embedding, p_emb);
    SPLIT(p_emb, p_embh, p_embl, BT * HH);

    // 4. xg = emb @ w_ih^T + b_ih + b_hh   [4064, 2048]
    {
        dim3 grid(4 * HH / 128, MPAD / 128);
        mma_gemm<<<grid, 256, mma_smem>>>(p_embh, p_embl, p_wihh, p_wihl,
                                          b_ih, b_hh, nullptr, p_xg, BT, 4 * HH, HH);
    }

    // 5. LSTM recurrence
    lstm_persistent_kernel<<<NBLK, 512, lstm_smem>>>(p_xg, w_hh, h_buf0, h_buf1, p_lstm);
    SPLIT(p_lstm, p_lstmh, p_lstml, BT * HH);

    // 6. q/k/v projections
    {
        dim3 gq(HH / 128, MPAD / 128);
        mma_gemm<<<gq, 256, mma_smem>>>(p_lstmh, p_lstml, p_inph, p_inpl,
                                        in_proj_b, nullptr, nullptr, p_q, BT, HH, HH);
        dim3 gk(HH / 128, BS / 128);
        mma_gemm<<<gk, 256, mma_smem>>>(p_ench, p_encl, p_inph + (size_t)HH * HH,
                                        p_inpl + (size_t)HH * HH,
                                        in_proj_b + HH, nullptr, nullptr, p_k, BS, HH, HH);
        mma_gemm<<<gk, 256, mma_smem>>>(p_ench, p_encl, p_inph + (size_t)2 * HH * HH,
                                        p_inpl + (size_t)2 * HH * HH,
                                        in_proj_b + 2 * HH, nullptr, nullptr, p_v, BS, HH, HH);
    }

    // 7. fused attention -> ctx
    {
        dim3 grid(4, NHH, BB);
        attn_kernel<<<grid, 256, attn_smem>>>(p_q, p_k, p_v, p_ctx);
    }
    SPLIT(p_ctx, p_ctxh, p_ctxl, BT * HH);

    // 8. combined = ctx @ out_proj^T + out_proj_b + lstm_out
    {
        dim3 grid(HH / 128, MPAD / 128);
        mma_gemm<<<grid, 256, mma_smem>>>(p_ctxh, p_ctxl, p_outph, p_outpl,
                                          out_proj_b, nullptr, p_lstm, p_comb, BT, HH, HH);
    }
    SPLIT(p_comb, p_combh, p_combl, BT * HH);

    // 9. out = combined @ fc_w^T + fc_b   [4064, 8000]
    {
        dim3 grid(VPAD / 128, MPAD / 128);
        mma_gemm<<<grid, 256, mma_smem>>>(p_combh, p_combl, p_fcwh, p_fcwl,
                                          fc_b, nullptr, nullptr, out, BT, VV, HH);
    }
    #undef SPLIT
}

// round 11
// speedup vs baseline: 2.5835x; 1.5748x over previous
#include <cuda_runtime.h>
#include <cuda_bf16.h>
#include <math.h>
#include <stdint.h>
#include <string.h>

// Problem constants
#define BB   32
#define TT   127
#define SS   256
#define HH   512
#define VV   8000
#define NHH  8
#define HDD  64
#define BT   (BB*TT)      // 4064
#define BS   (BB*SS)      // 8192
#define NBLK 128          // persistent LSTM grid (4 groups x 32 blocks)
#define MPAD 4096
#define VPAD 8064

// ---------------- scratch (device globals; no allocations allowed) ----------------
__device__ float g_emb [BT * HH];
__device__ float g_xg  [BT * 4 * HH];
__device__ float g_lstm[BT * HH];
__device__ float g_q   [BT * HH];
__device__ float g_k   [BS * HH];
__device__ float g_v   [BS * HH];
__device__ float g_ctx [BT * HH];
__device__ float g_comb[BT * HH];
__device__ unsigned g_flags[NBLK * 2 * 32];   // one padded flag per block (64 words apart)

// bf16 hi/lo split buffers
__device__ __nv_bfloat16 g_embh [MPAD * HH], g_embl [MPAD * HH];
__device__ __nv_bfloat16 g_lstmh[MPAD * HH], g_lstml[MPAD * HH];
__device__ __nv_bfloat16 g_ctxh [MPAD * HH], g_ctxl [MPAD * HH];
__device__ __nv_bfloat16 g_combh[MPAD * HH], g_combl[MPAD * HH];
__device__ __nv_bfloat16 g_ench [BS * HH],   g_encl [BS * HH];
__device__ __nv_bfloat16 g_wihh [4*HH*HH],   g_wihl [4*HH*HH];
__device__ __nv_bfloat16 g_whhh [4*HH*HH],   g_whhl [4*HH*HH];
__device__ __nv_bfloat16 g_inph [3*HH*HH],   g_inpl [3*HH*HH];
__device__ __nv_bfloat16 g_outph[HH*HH],     g_outpl[HH*HH];
__device__ __nv_bfloat16 g_fcwh [VPAD * HH], g_fcwl [VPAD * HH];
// LSTM h ping-pong, bf16 hi/lo, B-operand packed layout:
// [group][seg 16][batch 8][32 halves] -> group region 4096 halves
__device__ __nv_bfloat16 g_hbh[2][4 * 4096];
__device__ __nv_bfloat16 g_hbl[2][4 * 4096];

// ---------------- cp.async helpers ----------------
__device__ __forceinline__ void cp_async16(uint32_t dst_smem, const void* src_gmem) {
    asm volatile("cp.async.cg.shared.global [%0], [%1], 16;\n" :: "r"(dst_smem), "l"(src_gmem));
}
__device__ __forceinline__ void cp_async_commit() { asm volatile("cp.async.commit_group;\n"); }
#define CP_WAITN(n) asm volatile("cp.async.wait_group %0;\n" :: "n"(n))

__device__ __forceinline__ uint32_t s2u(const void* p) {
    uint32_t a;
    asm("{ .reg .u64 t; cvta.to.shared.u64 t, %1; cvt.u32.u64 %0, t; }" : "=r"(a) : "l"(p));
    return a;
}
__device__ __forceinline__ void st_bf16_cg(__nv_bfloat16* p, __nv_bfloat16 v) {
    unsigned short u; memcpy(&u, &v, 2);
    asm volatile("st.global.cg.u16 [%0], %1;" :: "l"(p), "h"(u) : "memory");
}

// ---------------- mma helpers ----------------
#define LDSM_X4(r0, r1, r2, r3, addr)                                              \
    asm volatile("ldmatrix.sync.aligned.m8n8.x4.shared.b16 {%0,%1,%2,%3}, [%4];"   \
        : "=r"(r0), "=r"(r1), "=r"(r2), "=r"(r3) : "r"(addr))
#define LDSM_X2(r0, r1, addr)                                                      \
    asm volatile("ldmatrix.sync.aligned.m8n8.x2.shared.b16 {%0,%1}, [%2];"         \
        : "=r"(r0), "=r"(r1) : "r"(addr))
#define MMA16816(d, a, b)                                                          \
    asm volatile("mma.sync.aligned.m16n8k16.row.col.f32.bf16.bf16.f32 "            \
        "{%0,%1,%2,%3},{%4,%5,%6,%7},{%8,%9},{%0,%1,%2,%3};"                       \
        : "+f"((d)[0]), "+f"((d)[1]), "+f"((d)[2]), "+f"((d)[3])                   \
        : "r"((a)[0]), "r"((a)[1]), "r"((a)[2]), "r"((a)[3]),                      \
          "r"((b)[0]), "r"((b)[1]))

// ---------------- init: zero h0 (bf16 buffers) and flags ----------------
__global__ void zero_kernel() {
    int i = blockIdx.x * blockDim.x + threadIdx.x;
    if (i < 2 * 4 * 4096) {
        ((__nv_bfloat16*)g_hbh)[i] = __float2bfloat16(0.f);
        ((__nv_bfloat16*)g_hbl)[i] = __float2bfloat16(0.f);
    }
    if (i < NBLK * 2 * 32) g_flags[i] = 0u;
}

// ---------------- embedding gather ----------------
__global__ void gather_kernel(const int* __restrict__ targets,
                              const float* __restrict__ table,
                              float* __restrict__ out) {
    int bt = blockIdx.x;
    int b = bt / TT, t = bt - b * TT;
    int tok = targets[b * 128 + t];
    const float4* src = (const float4*)(table + (size_t)tok * HH);
    float4* dst = (float4*)(out + (size_t)bt * HH);
    dst[threadIdx.x] = src[threadIdx.x];
}

// ---------------- fp32 -> bf16 hi/lo split ----------------
__global__ void split_kernel(const float* __restrict__ x,
                             __nv_bfloat16* __restrict__ hi,
                             __nv_bfloat16* __restrict__ lo, int n) {
    int i4 = (blockIdx.x * blockDim.x + threadIdx.x) * 4;
    if (i4 < n) {
        float4 v = *(const float4*)(x + i4);
        __nv_bfloat16 hx = __float2bfloat16_rn(v.x);
        __nv_bfloat16 hy = __float2bfloat16_rn(v.y);
        __nv_bfloat16 hz = __float2bfloat16_rn(v.z);
        __nv_bfloat16 hw = __float2bfloat16_rn(v.w);
        __nv_bfloat16 lx = __float2bfloat16_rn(v.x - __bfloat162float(hx));
        __nv_bfloat16 ly = __float2bfloat16_rn(v.y - __bfloat162float(hy));
        __nv_bfloat16 lz = __float2bfloat16_rn(v.z - __bfloat162float(hz));
        __nv_bfloat16 lw = __float2bfloat16_rn(v.w - __bfloat162float(hw));
        *(__nv_bfloat162*)(hi + i4)     = __halves2bfloat162(hx, hy);
        *(__nv_bfloat162*)(hi + i4 + 2) = __halves2bfloat162(hz, hw);
        *(__nv_bfloat162*)(lo + i4)     = __halves2bfloat162(lx, ly);
        *(__nv_bfloat162*)(lo + i4 + 2) = __halves2bfloat162(lz, lw);
    }
}

// ---------------- tensor-core GEMM via mma.sync (unchanged from R10) ----------------
#define AP   40
#define SEG  (128 * AP * 2)
__global__ __launch_bounds__(256) void mma_gemm(
    const __nv_bfloat16* __restrict__ Ah, const __nv_bfloat16* __restrict__ Al,
    const __nv_bfloat16* __restrict__ Bh, const __nv_bfloat16* __restrict__ Bl,
    const float* __restrict__ bias1, const float* __restrict__ bias2,
    const float* __restrict__ res, float* __restrict__ C,
    int M, int N, int K)
{
    extern __shared__ char smem[];
    const uint32_t sb = s2u(smem);
    const int tid  = threadIdx.x;
    const int wid  = tid >> 5;
    const int lane = tid & 31;
    const int wm = wid >> 2;
    const int wn = wid & 3;
    const int m0 = blockIdx.y * 128;
    const int n0 = blockIdx.x * 128;

    float acc[4][4][4];
    #pragma unroll
    for (int i = 0; i < 4; i++)
        #pragma unroll
        for (int j = 0; j < 4; j++)
            #pragma unroll
            for (int r = 0; r < 4; r++) acc[i][j][r] = 0.f;

    const __nv_bfloat16* srcAh = Ah + (size_t)m0 * K;
    const __nv_bfloat16* srcAl = Al + (size_t)m0 * K;
    const __nv_bfloat16* srcBh = Bh + (size_t)n0 * K;
    const __nv_bfloat16* srcBl = Bl + (size_t)n0 * K;

    auto issue = [&](int k0, int buf) {
        #pragma unroll
        for (int t = 0; t < 8; t++) {
            int idx = tid + t * 256;
            int mat = idx >> 9;
            int r   = (idx >> 2) & 127;
            int j   = idx & 3;
            uint32_t dst = sb + (uint32_t)(mat * 2 + buf) * SEG
                         + (uint32_t)(r * AP + j * 8) * 2;
            const __nv_bfloat16* s =
                (mat == 0 ? srcAh : mat == 1 ? srcAl : mat == 2 ? srcBh : srcBl)
                + (size_t)r * K + k0 + j * 8;
            cp_async16(dst, s);
        }
        cp_async_commit();
    };

    const uint32_t a_off = (uint32_t)(((wm * 64 + (lane & 15)) * AP + (lane >> 4) * 8) * 2);
    const uint32_t b_off = (uint32_t)(((wn * 32 + (lane & 7)) * AP + ((lane >> 3) & 1) * 8) * 2);

    const int NC = K / 32;
    issue(0, 0);
    #pragma unroll 1
    for (int c = 0; c < NC; c++) {
        const int buf = c & 1;
        if (c + 1 < NC) { issue((c + 1) * 32, buf ^ 1); CP_WAITN(1); }
        else           { CP_WAITN(0); }
        __syncthreads();

        #pragma unroll
        for (int ks = 0; ks < 2; ks++) {
            const uint32_t kb = (uint32_t)(ks * 32);
            uint32_t bh[4][2], bl[4][2];
            #pragma unroll
            for (int nt = 0; nt < 4; nt++) {
                uint32_t ba = sb + (uint32_t)(4 + buf) * SEG + b_off
                            + (uint32_t)(nt * 8 * AP * 2) + kb;
                LDSM_X2(bh[nt][0], bh[nt][1], ba);
                LDSM_X2(bl[nt][0], bl[nt][1], ba + 2u * SEG);
            }
            #pragma unroll
            for (int mt = 0; mt < 4; mt++) {
                uint32_t ah[4], al[4];
                uint32_t aa = sb + (uint32_t)buf * SEG + a_off
                            + (uint32_t)(mt * 16 * AP * 2) + kb;
                LDSM_X4(ah[0], ah[1], ah[2], ah[3], aa);
                LDSM_X4(al[0], al[1], al[2], al[3], aa + 2u * SEG);
                #pragma unroll
                for (int nt = 0; nt < 4; nt++) {
                    MMA16816(acc[mt][nt], ah, bh[nt]);
                    MMA16816(acc[mt][nt], ah, bl[nt]);
                    MMA16816(acc[mt][nt], al, bh[nt]);
                }
            }
        }
        __syncthreads();
    }

    const int tm = lane >> 2;
    const int tc = (lane & 3) * 2;
    #pragma unroll
    for (int mt = 0; mt < 4; mt++) {
        #pragma unroll
        for (int nt = 0; nt < 4; nt++) {
            int col = n0 + wn * 32 + nt * 8 + tc;
            if (col >= N) continue;
            float2 v0 = make_float2(acc[mt][nt][0], acc[mt][nt][1]);
            float2 v1 = make_float2(acc[mt][nt][2], acc[mt][nt][3]);
            if (bias1) {
                float2 b = *(const float2*)(bias1 + col);
                v0.x += b.x; v0.y += b.y; v1.x += b.x; v1.y += b.y;
            }
            if (bias2) {
                float2 b = *(const float2*)(bias2 + col);
                v0.x += b.x; v0.y += b.y; v1.x += b.x; v1.y += b.y;
            }
            int row0 = m0 + wm * 64 + mt * 16 + tm;
            if (row0 < M) {
                float2 o = v0;
                if (res) {
                    float2 rr = *(const float2*)(res + (size_t)row0 * N + col);
                    o.x += rr.x; o.y += rr.y;
                }
                *(float2*)(C + (size_t)row0 * N + col) = o;
            }
            int row1 = row0 + 8;
            if (row1 < M) {
                float2 o = v1;
                if (res) {
                    float2 rr = *(const float2*)(res + (size_t)row1 * N + col);
                    o.x += rr.x; o.y += rr.y;
                }
                *(float2*)(C + (size_t)row1 * N + col) = o;
            }
        }
    }
}

// ---------------- tensor-core persistent LSTM ----------------
// 4 groups x 32 blocks. Block = 16 h-cols (col_base..+16) x 8 batches of its group.
// Gate pre-activation: [64 gate-rows] x [8 batches] = W_slice[64,512] @ h[8,512]^T, 3-pass bf16.
// Gate rows: r = gate*16 + colL  (mt index == gate -> activations need no shuffles).
// Warp w owns K-chunk w (32 wide): A-fragments hoisted into registers for ALL steps.
// smem: w chunked (ldmatrix layout, freed conceptually after preload but kept),
//       h staging (B layout), reduction array (513-pitch, conflict-free).
#define LW_SEG  (64 * AP * 2)        // 5120 B per 32-k seg per matrix
#define LH_SEG  (8 * AP * 2)         // 640 B
#define SM_WH   0
#define SM_WL   81920
#define SM_HH   163840
#define SM_HL   174080
#define SM_RED  184320               // 16*513 floats = 32832 B
#define LSTM_SMEM (SM_RED + 16 * 513 * 4)   // 217152

__global__ __launch_bounds__(512) void lstm_mma_kernel(
    const float* __restrict__ xg,
    const __nv_bfloat16* __restrict__ whh_h, const __nv_bfloat16* __restrict__ whh_l,
    float* __restrict__ lstm_out)
{
    extern __shared__ char smem[];
    const uint32_t sb = s2u(smem);
    float* red = (float*)(smem + SM_RED);

    const int tid   = threadIdx.x;
    const int wid   = tid >> 5;
    const int lane  = tid & 31;
    const int group = blockIdx.x >> 5;
    const int gslot = blockIdx.x & 31;
    const int col_base = gslot * 16;

    // ---- load w slice (64 rows x 512) hi+lo into chunked smem ----
    for (int it = tid; it < 16 * 64 * 4; it += 512) {
        int s = it >> 8;              // seg 0..15
        int r = (it >> 2) & 63;       // smem row = gate*16 + colL
        int j = it & 3;
        int gate = r >> 4, colL = r & 15;
        size_t src = (size_t)(gate * HH + col_base + colL) * HH + s * 32 + j * 8;
        uint32_t dst = (uint32_t)(s * LW_SEG + r * (AP * 2) + j * 16);
        cp_async16(sb + SM_WH + dst, whh_h + src);
        cp_async16(sb + SM_WL + dst, whh_l + src);
    }
    cp_async_commit();
    CP_WAITN(0);
    __syncthreads();

    // ---- hoist A fragments (this warp's seg) into registers for all steps ----
    const int seg = wid;   // warp w owns k chunk [seg*32, seg*32+32)
    const uint32_t a_off = (uint32_t)(((lane & 15) * AP + (lane >> 4) * 8) * 2);
    uint32_t Afh[4][2][4], Afl[4][2][4];
    #pragma unroll
    for (int g = 0; g < 4; g++) {
        #pragma unroll
        for (int ks = 0; ks < 2; ks++) {
            uint32_t aa = sb + (uint32_t)(seg * LW_SEG + g * 16 * AP * 2) + a_off
                        + (uint32_t)(ks * 32);
            LDSM_X4(Afh[g][ks][0], Afh[g][ks][1], Afh[g][ks][2], Afh[g][ks][3], aa);
            LDSM_X4(Afl[g][ks][0], Afl[g][ks][1], Afl[g][ks][2], Afl[g][ks][3],
                    aa + (uint32_t)(SM_WL - SM_WH));
        }
    }

    const uint32_t b_off = (uint32_t)(((lane & 7) * AP + ((lane >> 3) & 1) * 8) * 2);

    // activation cell ownership (tid<128): colL = tid>>3, b = tid&7
    const int acolL = tid >> 3;
    const int ab    = tid & 7;
    const int gcol  = col_base + acolL;
    const int abatch = group * 8 + ab;
    const int hseg  = gcol >> 5;
    const int hc32  = gcol & 31;
    const size_t xgb = (size_t)(abatch * TT) * (4 * HH) + gcol;
    unsigned* my_flag = &g_flags[blockIdx.x * 64];
    float c_reg = 0.f;

    const __nv_bfloat16* hbh_rd[2] = { g_hbh[0] + group * 4096, g_hbh[1] + group * 4096 };
    const __nv_bfloat16* hbl_rd[2] = { g_hbl[0] + group * 4096, g_hbl[1] + group * 4096 };
    __nv_bfloat16* hbh_wr[2] = { g_hbh[0] + group * 4096, g_hbh[1] + group * 4096 };
    __nv_bfloat16* hbl_wr[2] = { g_hbl[0] + group * 4096, g_hbl[1] + group * 4096 };

    for (int t = 0; t < TT; t++) {
        const int rb = t & 1;          // read buffer
        const int wb = rb ^ 1;         // write buffer

        if (t > 0) {
            if (tid < 32) {
                const unsigned* fp = &g_flags[(group * 32 + tid) * 64];
                unsigned v;
                do {
                    asm volatile("ld.acquire.gpu.global.u32 %0, [%1];"
                                 : "=r"(v) : "l"(fp) : "memory");
                } while (v < (unsigned)t);
            }
            __syncthreads();
        }

        // stage h hi+lo (16 segs x 8 b x 4 x16B granules each matrix)
        #pragma unroll
        for (int i = 0; i < 2; i++) {
            int it = tid + i * 512;                 // 0..1023
            int m  = it >> 9;                       // 0 hi, 1 lo
            int idx = it & 511;
            int s = idx >> 5, b = (idx >> 2) & 7, j = idx & 3;
            const __nv_bfloat16* src = (m ? hbl_rd[rb] : hbh_rd[rb])
                                     + s * 256 + b * 32 + j * 8;
            uint32_t dst = sb + (uint32_t)(m ? SM_HL : SM_HH)
                         + (uint32_t)(s * LH_SEG + b * (AP * 2) + j * 16);
            cp_async16(dst, src);
        }
        cp_async_commit();

        // prefetch xg for activations
        float xv0 = 0.f, xv1 = 0.f, xv2 = 0.f, xv3 = 0.f;
        if (tid < 128) {
            const float* xp = xg + xgb + (size_t)t * (4 * HH);
            xv0 = __ldg(xp);
            xv1 = __ldg(xp + HH);
            xv2 = __ldg(xp + 2 * HH);
            xv3 = __ldg(xp + 3 * HH);
        }

        CP_WAITN(0);
        __syncthreads();

        // mma: this warp's 32-k slice, all 4 gates, 3 passes
        float acc[4][4];
        #pragma unroll
        for (int g = 0; g < 4; g++)
            #pragma unroll
            for (int r = 0; r < 4; r++) acc[g][r] = 0.f;

        #pragma unroll
        for (int ks = 0; ks < 2; ks++) {
            uint32_t ba = sb + SM_HH + (uint32_t)(seg * LH_SEG) + b_off + (uint32_t)(ks * 32);
            uint32_t bh[2], bl[2];
            LDSM_X2(bh[0], bh[1], ba);
            LDSM_X2(bl[0], bl[1], ba + (uint32_t)(SM_HL - SM_HH));
            #pragma unroll
            for (int g = 0; g < 4; g++) {
                MMA16816(acc[g], Afh[g][ks], bh);
                MMA16816(acc[g], Afh[g][ks], bl);
                MMA16816(acc[g], Afl[g][ks], bh);
            }
        }

        // store partials: red[wid*513 + g*128 + row*8 + col]
        {
            const int tm = lane >> 2;
            const int tc = (lane & 3) * 2;
            float* rp = red + wid * 513;
            #pragma unroll
            for (int g = 0; g < 4; g++) {
                rp[g * 128 + tm * 8 + tc]           = acc[g][0];
                rp[g * 128 + tm * 8 + tc + 1]       = acc[g][1];
                rp[g * 128 + (tm + 8) * 8 + tc]     = acc[g][2];
                rp[g * 128 + (tm + 8) * 8 + tc + 1] = acc[g][3];
            }
        }
        __syncthreads();

        // reduce + activation (tid<128, one cell each)
        if (tid < 128) {
            const int p = acolL * 8 + ab;
            float gv[4] = { xv0, xv1, xv2, xv3 };
            #pragma unroll
            for (int w = 0; w < 16; w++) {
                const float* rp = red + w * 513 + p;
                gv[0] += rp[0];
                gv[1] += rp[128];
                gv[2] += rp[256];
                gv[3] += rp[384];
            }
            float ig = 1.f / (1.f + __expf(-gv[0]));
            float fg = 1.f / (1.f + __expf(-gv[1]));
            float gg = tanhf(gv[2]);
            float og = 1.f / (1.f + __expf(-gv[3]));
            c_reg = fg * c_reg + ig * gg;
            float hn = og * tanhf(c_reg);
            // fp32 for downstream
            lstm_out[(size_t)(abatch * TT + t) * HH + gcol] = hn;
            // bf16 split into next step's B buffer
            __nv_bfloat16 hh_ = __float2bfloat16_rn(hn);
            __nv_bfloat16 hl_ = __float2bfloat16_rn(hn - __bfloat162float(hh_));
            int off = hseg * 256 + ab * 32 + hc32;
            st_bf16_cg(hbh_wr[wb] + off, hh_);
            st_bf16_cg(hbl_wr[wb] + off, hl_);
        }
        __syncthreads();

        if (tid == 0) {
            asm volatile("fence.acq_rel.gpu;" ::: "memory");
            asm volatile("st.release.gpu.global.u32 [%0], %1;"
                         :: "l"(my_flag), "r"((unsigned)(t + 1)) : "memory");
        }
    }
}

// ---------------- fused attention (unchanged) ----------------
#define KTP 257
#define QSP 68
#define PSP 260
__global__ __launch_bounds__(256) void attn_kernel(
    const float* __restrict__ q, const float* __restrict__ kmat,
    const float* __restrict__ vmat, float* __restrict__ ctx)
{
    extern __shared__ float smemf[];
    float* Kt   = smemf;
    float* Vt   = Kt + 64 * KTP;
    float* qs   = Vt + 64 * KTP;
    float* ps   = qs + 32 * QSP;
    float* sums = ps + 32 * PSP;

    const int t0 = blockIdx.x * 32;
    const int h  = blockIdx.y;
    const int b  = blockIdx.z;
    const int tid = threadIdx.x;

    for (int idx = tid; idx < 256 * 16; idx += 256) {
        int s = idx >> 4; int d4 = (idx & 15) << 2;
        size_t off = (size_t)(b * SS + s) * HH + h * HDD + d4;
        float4 kv = *(const float4*)(kmat + off);
        Kt[(d4 + 0) * KTP + s] = kv.x; Kt[(d4 + 1) * KTP + s] = kv.y;
        Kt[(d4 + 2) * KTP + s] = kv.z; Kt[(d4 + 3) * KTP + s] = kv.w;
        float4 vv = *(const float4*)(vmat + off);
        Vt[(d4 + 0) * KTP + s] = vv.x; Vt[(d4 + 1) * KTP + s] = vv.y;
        Vt[(d4 + 2) * KTP + s] = vv.z; Vt[(d4 + 3) * KTP + s] = vv.w;
    }
    for (int idx = tid; idx < 32 * 16; idx += 256) {
        int r = idx >> 4; int d4 = (idx & 15) << 2;
        int trow = t0 + r;
        float4 qv = make_float4(0.f, 0.f, 0.f, 0.f);
        if (trow < TT)
            qv = *(const float4*)(q + (size_t)(b * TT + trow) * HH + h * HDD + d4);
        float* d = qs + r * QSP + d4;
        d[0] = qv.x; d[1] = qv.y; d[2] = qv.z; d[3] = qv.w;
    }
    __syncthreads();

    const int r  = tid >> 3;
    const int lc = tid & 7;

    float qreg[64];
    #pragma unroll
    for (int d = 0; d < 64; d++) qreg[d] = qs[r * QSP + d];

    float sc[32];
    for (int si = 0; si < 32; si++) {
        int s = si * 8 + lc;
        float acc = 0.f;
        #pragma unroll
        for (int d = 0; d < 64; d++) acc += qreg[d] * Kt[d * KTP + s];
        sc[si] = acc * 0.125f;
    }
    float m = -1e30f;
    #pragma unroll
    for (int si = 0; si < 32; si++) m = fmaxf(m, sc[si]);
    m = fmaxf(m, __shfl_xor_sync(0xffffffff, m, 1));
    m = fmaxf(m, __shfl_xor_sync(0xffffffff, m, 2));
    m = fmaxf(m, __shfl_xor_sync(0xffffffff, m, 4));
    float ssum = 0.f;
    #pragma unroll
    for (int si = 0; si < 32; si++) {
        float e = __expf(sc[si] - m);
        ssum += e;
        ps[r * PSP + si * 8 + lc] = e;
    }
    ssum += __shfl_xor_sync(0xffffffff, ssum, 1);
    ssum += __shfl_xor_sync(0xffffffff, ssum, 2);
    ssum += __shfl_xor_sync(0xffffffff, ssum, 4);
    if (lc == 0) sums[r] = ssum;
    __syncthreads();

    float accv[8];
    #pragma unroll
    for (int j = 0; j < 8; j++) accv[j] = 0.f;
    const float* prow = ps + r * PSP;
    #pragma unroll 4
    for (int s = 0; s < 256; s++) {
        float pv = prow[s];
        #pragma unroll
        for (int j = 0; j < 8; j++)
            accv[j] += pv * Vt[(lc + 8 * j) * KTP + s];
    }
    float inv = 1.0f / sums[r];
    int trow = t0 + r;
    if (trow < TT) {
        float* dst = ctx + (size_t)(b * TT + trow) * HH + h * HDD;
        #pragma unroll
        for (int j = 0; j < 8; j++) dst[lc + 8 * j] = accv[j] * inv;
    }
}

// ---------------- launch ----------------
extern "C" void kernel_launch(void* const* d_in, const int* in_sizes, int n_in,
                              void* d_out, int out_size) {
    const int*   targets  = (const int*)  d_in[0];
    const float* enc      = (const float*)d_in[1];
    const float* embedding= (const float*)d_in[2];
    const float* w_ih     = (const float*)d_in[3];
    const float* w_hh     = (const float*)d_in[4];
    const float* b_ih     = (const float*)d_in[5];
    const float* b_hh     = (const float*)d_in[6];
    const float* in_proj_w= (const float*)d_in[7];
    const float* in_proj_b= (const float*)d_in[8];
    const float* out_proj_w=(const float*)d_in[9];
    const float* out_proj_b=(const float*)d_in[10];
    const float* fc_w     = (const float*)d_in[11];
    const float* fc_b     = (const float*)d_in[12];
    float* out = (float*)d_out;

    float *p_emb, *p_xg, *p_lstm, *p_q, *p_k, *p_v, *p_ctx, *p_comb;
    cudaGetSymbolAddress((void**)&p_emb,  g_emb);
    cudaGetSymbolAddress((void**)&p_xg,   g_xg);
    cudaGetSymbolAddress((void**)&p_lstm, g_lstm);
    cudaGetSymbolAddress((void**)&p_q,    g_q);
    cudaGetSymbolAddress((void**)&p_k,    g_k);
    cudaGetSymbolAddress((void**)&p_v,    g_v);
    cudaGetSymbolAddress((void**)&p_ctx,  g_ctx);
    cudaGetSymbolAddress((void**)&p_comb, g_comb);
    __nv_bfloat16 *p_embh, *p_embl, *p_lstmh, *p_lstml, *p_ctxh, *p_ctxl,
                  *p_combh, *p_combl, *p_ench, *p_encl, *p_wihh, *p_wihl,
                  *p_whhh, *p_whhl, *p_inph, *p_inpl, *p_outph, *p_outpl,
                  *p_fcwh, *p_fcwl;
    cudaGetSymbolAddress((void**)&p_embh,  g_embh);
    cudaGetSymbolAddress((void**)&p_embl,  g_embl);
    cudaGetSymbolAddress((void**)&p_lstmh, g_lstmh);
    cudaGetSymbolAddress((void**)&p_lstml, g_lstml);
    cudaGetSymbolAddress((void**)&p_ctxh,  g_ctxh);
    cudaGetSymbolAddress((void**)&p_ctxl,  g_ctxl);
    cudaGetSymbolAddress((void**)&p_combh, g_combh);
    cudaGetSymbolAddress((void**)&p_combl, g_combl);
    cudaGetSymbolAddress((void**)&p_ench,  g_ench);
    cudaGetSymbolAddress((void**)&p_encl,  g_encl);
    cudaGetSymbolAddress((void**)&p_wihh,  g_wihh);
    cudaGetSymbolAddress((void**)&p_wihl,  g_wihl);
    cudaGetSymbolAddress((void**)&p_whhh,  g_whhh);
    cudaGetSymbolAddress((void**)&p_whhl,  g_whhl);
    cudaGetSymbolAddress((void**)&p_inph,  g_inph);
    cudaGetSymbolAddress((void**)&p_inpl,  g_inpl);
    cudaGetSymbolAddress((void**)&p_outph, g_outph);
    cudaGetSymbolAddress((void**)&p_outpl, g_outpl);
    cudaGetSymbolAddress((void**)&p_fcwh,  g_fcwh);
    cudaGetSymbolAddress((void**)&p_fcwl,  g_fcwl);

    const int attn_smem = (64 * KTP * 2 + 32 * QSP + 32 * PSP + 32) * (int)sizeof(float);
    const int mma_smem  = 8 * SEG;     // 81920
    cudaFuncSetAttribute(attn_kernel,     cudaFuncAttributeMaxDynamicSharedMemorySize, attn_smem);
    cudaFuncSetAttribute(mma_gemm,        cudaFuncAttributeMaxDynamicSharedMemorySize, mma_smem);
    cudaFuncSetAttribute(lstm_mma_kernel, cudaFuncAttributeMaxDynamicSharedMemorySize, LSTM_SMEM);

    #define SPLIT(src, hi, lo, n) split_kernel<<<((n)/4 + 255) / 256, 256>>>(src, hi, lo, n)

    // 1. zero h0 (bf16 buffers) + flags
    zero_kernel<<<(2 * 4 * 4096 + 255) / 256, 256>>>();

    // 2. weight/input splits
    SPLIT(w_ih,       p_wihh,  p_wihl,  4 * HH * HH);
    SPLIT(w_hh,       p_whhh,  p_whhl,  4 * HH * HH);
    SPLIT(in_proj_w,  p_inph,  p_inpl,  3 * HH * HH);
    SPLIT(out_proj_w, p_outph, p_outpl, HH * HH);
    SPLIT(fc_w,       p_fcwh,  p_fcwl,  VV * HH);
    SPLIT(enc,        p_ench,  p_encl,  BS * HH);

    // 3. gather embeddings + split
    gather_kernel<<<BT, 128>>>(targets, embedding, p_emb);
    SPLIT(p_emb, p_embh, p_embl, BT * HH);

    // 4. xg = emb @ w_ih^T + b_ih + b_hh
    {
        dim3 grid(4 * HH / 128, MPAD / 128);
        mma_gemm<<<grid, 256, mma_smem>>>(p_embh, p_embl, p_wihh, p_wihl,
                                          b_ih, b_hh, nullptr, p_xg, BT, 4 * HH, HH);
    }

    // 5. LSTM recurrence — tensor-core persistent kernel
    lstm_mma_kernel<<<NBLK, 512, LSTM_SMEM>>>(p_xg, p_whhh, p_whhl, p_lstm);
    SPLIT(p_lstm, p_lstmh, p_lstml, BT * HH);

    // 6. q/k/v projections
    {
        dim3 gq(HH / 128, MPAD / 128);
        mma_gemm<<<gq, 256, mma_smem>>>(p_lstmh, p_lstml, p_inph, p_inpl,
                                        in_proj_b, nullptr, nullptr, p_q, BT, HH, HH);
        dim3 gk(HH / 128, BS / 128);
        mma_gemm<<<gk, 256, mma_smem>>>(p_ench, p_encl, p_inph + (size_t)HH * HH,
                                        p_inpl + (size_t)HH * HH,
                                        in_proj_b + HH, nullptr, nullptr, p_k, BS, HH, HH);
        mma_gemm<<<gk, 256, mma_smem>>>(p_ench, p_encl, p_inph + (size_t)2 * HH * HH,
                                        p_inpl + (size_t)2 * HH * HH,
                                        in_proj_b + 2 * HH, nullptr, nullptr, p_v, BS, HH, HH);
    }

    // 7. fused attention -> ctx
    {
        dim3 grid(4, NHH, BB);
        attn_kernel<<<grid, 256, attn_smem>>>(p_q, p_k, p_v, p_ctx);
    }
    SPLIT(p_ctx, p_ctxh, p_ctxl, BT * HH);

    // 8. combined = ctx @ out_proj^T + out_proj_b + lstm_out
    {
        dim3 grid(HH / 128, MPAD / 128);
        mma_gemm<<<grid, 256, mma_smem>>>(p_ctxh, p_ctxl, p_outph, p_outpl,
                                          out_proj_b, nullptr, p_lstm, p_comb, BT, HH, HH);
    }
    SPLIT(p_comb, p_combh, p_combl, BT * HH);

    // 9. out = combined @ fc_w^T + fc_b
    {
        dim3 grid(VPAD / 128, MPAD / 128);
        mma_gemm<<<grid, 256, mma_smem>>>(p_combh, p_combl, p_fcwh, p_fcwl,
                                          fc_b, nullptr, nullptr, out, BT, VV, HH);
    }
    #undef SPLIT
}